// round 14
// baseline (speedup 1.0000x reference)
#include <cuda_runtime.h>
#include <math.h>

#define Bn 2
#define Ll 16384
#define DI 128
#define Kk 4
#define NB 4
#define NC 128          // chunks per sequence
#define LC 128          // chunk length

typedef unsigned long long ull;

// -------------------- scratch (device globals; no allocation) --------------------
__device__ float g_t  [Bn*Ll*64];        // residual stream (b,l,64)
__device__ float g_h  [Bn*Ll*64];        // LN scratch (b,l,64)
__device__ float g_xz [Bn*Ll*256];       // in_proj out / MLP hidden (b,l,256)
__device__ float g_xcT[Bn*Ll*DI];        // conv+silu out, NHWC (b,l,d)
__device__ float g_u1t[Bn*Ll*DI];        // wh-order (b, w*128+h, d)
__device__ float g_bc [Bn*Kk*Ll*32];     // B(16)+C(16) per (b,k,l)
__device__ float g_dts[Bn*Kk*Ll*4];      // raw dt-rank values per (b,k,l)
__device__ float g_ys [(size_t)Bn*Kk*Ll*DI];   // (b,k,l,d)
__device__ float g_yo [Bn*Ll*DI];        // gated+LN (b,l,d)
__device__ float g_o1 [Bn*32*Ll];        // head conv1 out (b,32,l)
__device__ float g_sum  [Bn*Kk*NC*DI*32];  // per-chunk {P[16], hEnd[16]}
__device__ float g_hinit[Bn*Kk*NC*DI*16];  // per-chunk init state
__device__ int   g_cnt[8];                 // per-(b,k) completion counters (self-resetting)

__device__ __forceinline__ float geluf(float v){
    return 0.5f*v*(1.f + erff(v*0.70710678118654752f));
}
__device__ __forceinline__ ull fma2(ull a, ull b, ull c){
    ull d; asm("fma.rn.f32x2 %0,%1,%2,%3;" : "=l"(d) : "l"(a), "l"(b), "l"(c)); return d;
}
__device__ __forceinline__ ull mul2(ull a, ull b){
    ull d; asm("mul.rn.f32x2 %0,%1,%2;" : "=l"(d) : "l"(a), "l"(b)); return d;
}
__device__ __forceinline__ ull pack2(float lo, float hi){
    ull d; asm("mov.b64 %0,{%1,%2};" : "=l"(d) : "f"(lo), "f"(hi)); return d;
}
__device__ __forceinline__ float2 unpack2(ull v){
    float2 r; asm("mov.b64 {%0,%1},%2;" : "=f"(r.x), "=f"(r.y) : "l"(v)); return r;
}

// -------------------- stem: f = 1x1 conv over concat(x,y) --------------------
__global__ void k_reduce(const float* __restrict__ x, const float* __restrict__ y,
                         const float* __restrict__ rw, float* __restrict__ f){
    __shared__ float sx[128][33];
    __shared__ float so[64][33];
    int b = blockIdx.y; int l0 = blockIdx.x*32;
    int tid = threadIdx.x;
    for (int e = tid; e < 128*32; e += 256){
        int c = e>>5, li = e&31;
        sx[c][li] = (c < 64) ? x[((size_t)(b*64+c))*Ll + l0+li]
                             : y[((size_t)(b*64+c-64))*Ll + l0+li];
    }
    __syncthreads();
    int o = tid>>2, lb = (tid&3)*8;
    float acc[8] = {0.f,0.f,0.f,0.f,0.f,0.f,0.f,0.f};
    for (int c = 0; c < 128; c++){
        float w = __ldg(rw + o*128 + c);
        #pragma unroll
        for (int j = 0; j < 8; j++) acc[j] += w*sx[c][lb+j];
    }
    #pragma unroll
    for (int j = 0; j < 8; j++) so[o][lb+j] = acc[j];
    __syncthreads();
    for (int e = tid; e < 64*32; e += 256){
        int oo = e>>5, li = e&31;
        f[((size_t)(b*64+oo))*Ll + l0+li] = so[oo][li];
    }
}

// -------------------- patch embed 1x1 conv (reads f), writes (b,l,64) --------------------
__global__ void k_patch(const float* __restrict__ f, const float* __restrict__ pw,
                        float* __restrict__ out){
    __shared__ float sx[64][33];
    __shared__ float so[64][33];
    int b = blockIdx.y; int l0 = blockIdx.x*32;
    int tid = threadIdx.x;
    for (int e = tid; e < 64*32; e += 256){
        int c = e>>5, li = e&31;
        sx[c][li] = f[((size_t)(b*64+c))*Ll + l0+li];
    }
    __syncthreads();
    int o = tid>>2, lb = (tid&3)*8;
    float acc[8] = {0.f,0.f,0.f,0.f,0.f,0.f,0.f,0.f};
    for (int c = 0; c < 64; c++){
        float w = __ldg(pw + o*64 + c);
        #pragma unroll
        for (int j = 0; j < 8; j++) acc[j] += w*sx[c][lb+j];
    }
    #pragma unroll
    for (int j = 0; j < 8; j++) so[o][lb+j] = acc[j];
    __syncthreads();
    for (int e = tid; e < 64*32; e += 256){
        int o2 = e&63, li = e>>6;
        out[((size_t)(b*Ll) + l0 + li)*64 + o2] = so[o2][li];
    }
}

// ------------- LayerNorm over last dim of 64; warp-per-row, shfl-only --------------------
__global__ void k_ln64(const float* __restrict__ in, float* __restrict__ out,
                       const float* __restrict__ g, const float* __restrict__ bb){
    int warp = threadIdx.x>>5, lane = threadIdx.x&31;
    size_t row = (size_t)blockIdx.x*8 + warp;
    float2 v = *(const float2*)(in + row*64 + lane*2);
    float s = v.x + v.y, s2 = v.x*v.x + v.y*v.y;
    #pragma unroll
    for (int o = 16; o; o >>= 1){ s += __shfl_xor_sync(~0u, s, o); s2 += __shfl_xor_sync(~0u, s2, o); }
    float mean = s*(1.f/64.f);
    float rstd = rsqrtf(s2*(1.f/64.f) - mean*mean + 1e-5f);
    float2 gg = *(const float2*)(g + lane*2);
    float2 bv = *(const float2*)(bb + lane*2);
    float2 ov;
    ov.x = (v.x-mean)*rstd*gg.x + bv.x;
    ov.y = (v.y-mean)*rstd*gg.y + bv.y;
    *(float2*)(out + row*64 + lane*2) = ov;
}

// ------ GEMM 128x64 tile, 8x4/thread, double-buffered; optional fused row-LN epilogue -----
__global__ void k_gemm(const float* __restrict__ A, const float* __restrict__ Wm,
                       const float* __restrict__ bias, float* __restrict__ C,
                       int M, int Nq, int Kd, int act, int accum,
                       const float* __restrict__ lng, const float* __restrict__ lnb,
                       float* __restrict__ lnout){
    __shared__ float As[2][16][132];
    __shared__ float Ws[2][16][68];
    int m0 = blockIdx.y<<7, n0 = blockIdx.x<<6;
    int tid = threadIdx.x;
    int tm = tid>>4, tn = tid&15;
    float acc[8][4] = {};

    {
        #pragma unroll
        for (int rep = 0; rep < 2; rep++){
            int f4 = tid + rep*256;
            int row = f4>>2, q = f4&3;
            float4 av = *(const float4*)(A + (size_t)(m0+row)*Kd + 0 + q*4);
            As[0][q*4+0][row]=av.x; As[0][q*4+1][row]=av.y; As[0][q*4+2][row]=av.z; As[0][q*4+3][row]=av.w;
        }
        int row = tid>>2, q = tid&3;
        float4 wv = *(const float4*)(Wm + (size_t)(n0+row)*Kd + 0 + q*4);
        Ws[0][q*4+0][row]=wv.x; Ws[0][q*4+1][row]=wv.y; Ws[0][q*4+2][row]=wv.z; Ws[0][q*4+3][row]=wv.w;
    }
    __syncthreads();

    int buf = 0;
    for (int kk = 0; kk < Kd; kk += 16, buf ^= 1){
        float4 pa0, pa1, pw;
        bool more = (kk + 16) < Kd;
        if (more){
            { int row = tid>>2, q = tid&3;
              pa0 = *(const float4*)(A + (size_t)(m0+row)*Kd + kk+16 + q*4); }
            { int f4 = tid + 256; int row = f4>>2, q = f4&3;
              pa1 = *(const float4*)(A + (size_t)(m0+row)*Kd + kk+16 + q*4); }
            { int row = tid>>2, q = tid&3;
              pw = *(const float4*)(Wm + (size_t)(n0+row)*Kd + kk+16 + q*4); }
        }
        #pragma unroll
        for (int k = 0; k < 16; k++){
            float a[8], w[4];
            *(float4*)(a+0) = *(const float4*)&As[buf][k][tm*8+0];
            *(float4*)(a+4) = *(const float4*)&As[buf][k][tm*8+4];
            *(float4*)(w+0) = *(const float4*)&Ws[buf][k][tn*4];
            #pragma unroll
            for (int i = 0; i < 8; i++){
                acc[i][0] = fmaf(a[i], w[0], acc[i][0]);
                acc[i][1] = fmaf(a[i], w[1], acc[i][1]);
                acc[i][2] = fmaf(a[i], w[2], acc[i][2]);
                acc[i][3] = fmaf(a[i], w[3], acc[i][3]);
            }
        }
        if (more){
            int nb = buf^1;
            { int row = tid>>2, q = tid&3;
              As[nb][q*4+0][row]=pa0.x; As[nb][q*4+1][row]=pa0.y; As[nb][q*4+2][row]=pa0.z; As[nb][q*4+3][row]=pa0.w; }
            { int f4 = tid + 256; int row = f4>>2, q = f4&3;
              As[nb][q*4+0][row]=pa1.x; As[nb][q*4+1][row]=pa1.y; As[nb][q*4+2][row]=pa1.z; As[nb][q*4+3][row]=pa1.w; }
            { int row = tid>>2, q = tid&3;
              Ws[nb][q*4+0][row]=pw.x; Ws[nb][q*4+1][row]=pw.y; Ws[nb][q*4+2][row]=pw.z; Ws[nb][q*4+3][row]=pw.w; }
            __syncthreads();
        }
    }
    float bv[4] = {0.f,0.f,0.f,0.f};
    if (bias){
        #pragma unroll
        for (int j = 0; j < 4; j++) bv[j] = bias[n0 + tn*4 + j];
    }
    float gv[4], gb[4];
    if (lng){
        #pragma unroll
        for (int j = 0; j < 4; j++){ gv[j] = lng[tn*4 + j]; gb[j] = lnb[tn*4 + j]; }
    }
    #pragma unroll
    for (int i = 0; i < 8; i++){
        int m = m0 + tm*8 + i;
        float4* p = (float4*)(C + (size_t)m*Nq + n0 + tn*4);
        float v0 = acc[i][0]+bv[0], v1 = acc[i][1]+bv[1], v2 = acc[i][2]+bv[2], v3 = acc[i][3]+bv[3];
        if (act == 1){ v0=geluf(v0); v1=geluf(v1); v2=geluf(v2); v3=geluf(v3); }
        if (accum){ float4 old = *p; v0+=old.x; v1+=old.y; v2+=old.z; v3+=old.w; }
        *p = make_float4(v0, v1, v2, v3);
        if (lng){
            float rs  = v0+v1+v2+v3;
            float rs2 = v0*v0+v1*v1+v2*v2+v3*v3;
            #pragma unroll
            for (int o = 1; o < 16; o <<= 1){
                rs  += __shfl_xor_sync(~0u, rs,  o);
                rs2 += __shfl_xor_sync(~0u, rs2, o);
            }
            float mean = rs*(1.f/64.f);
            float rstd = rsqrtf(rs2*(1.f/64.f) - mean*mean + 1e-5f);
            float4 hv;
            hv.x = (v0-mean)*rstd*gv[0] + gb[0];
            hv.y = (v1-mean)*rstd*gv[1] + gb[1];
            hv.z = (v2-mean)*rstd*gv[2] + gb[2];
            hv.w = (v3-mean)*rstd*gv[3] + gb[3];
            *(float4*)(lnout + (size_t)m*64 + tn*4) = hv;
        }
    }
}

// ------ GEMM 128x128 tile, 8x8 per thread, double-buffered (N multiple of 128) -----------
__global__ void __launch_bounds__(256) k_gemm128(
                       const float* __restrict__ A, const float* __restrict__ Wm,
                       const float* __restrict__ bias, float* __restrict__ C,
                       int M, int Nq, int Kd, int act){
    __shared__ float As[2][16][132];
    __shared__ float Ws[2][16][132];
    int m0 = blockIdx.y<<7, n0 = blockIdx.x<<7;
    int tid = threadIdx.x;
    int tm = tid>>4, tn = tid&15;
    float acc[8][8] = {};

    {
        #pragma unroll
        for (int rep = 0; rep < 2; rep++){
            int f4 = tid + rep*256;
            int row = f4>>2, q = f4&3;
            float4 av = *(const float4*)(A + (size_t)(m0+row)*Kd + 0 + q*4);
            As[0][q*4+0][row]=av.x; As[0][q*4+1][row]=av.y; As[0][q*4+2][row]=av.z; As[0][q*4+3][row]=av.w;
            float4 wv = *(const float4*)(Wm + (size_t)(n0+row)*Kd + 0 + q*4);
            Ws[0][q*4+0][row]=wv.x; Ws[0][q*4+1][row]=wv.y; Ws[0][q*4+2][row]=wv.z; Ws[0][q*4+3][row]=wv.w;
        }
    }
    __syncthreads();

    int buf = 0;
    for (int kk = 0; kk < Kd; kk += 16, buf ^= 1){
        float4 pa0, pa1, pw0, pw1;
        bool more = (kk + 16) < Kd;
        if (more){
            { int row = tid>>2, q = tid&3;
              pa0 = *(const float4*)(A  + (size_t)(m0+row)*Kd + kk+16 + q*4);
              pw0 = *(const float4*)(Wm + (size_t)(n0+row)*Kd + kk+16 + q*4); }
            { int f4 = tid + 256; int row = f4>>2, q = f4&3;
              pa1 = *(const float4*)(A  + (size_t)(m0+row)*Kd + kk+16 + q*4);
              pw1 = *(const float4*)(Wm + (size_t)(n0+row)*Kd + kk+16 + q*4); }
        }
        #pragma unroll
        for (int k = 0; k < 16; k++){
            float a[8], w[8];
            *(float4*)(a+0) = *(const float4*)&As[buf][k][tm*8+0];
            *(float4*)(a+4) = *(const float4*)&As[buf][k][tm*8+4];
            *(float4*)(w+0) = *(const float4*)&Ws[buf][k][tn*8+0];
            *(float4*)(w+4) = *(const float4*)&Ws[buf][k][tn*8+4];
            #pragma unroll
            for (int i = 0; i < 8; i++){
                #pragma unroll
                for (int j = 0; j < 8; j++)
                    acc[i][j] = fmaf(a[i], w[j], acc[i][j]);
            }
        }
        if (more){
            int nb = buf^1;
            { int row = tid>>2, q = tid&3;
              As[nb][q*4+0][row]=pa0.x; As[nb][q*4+1][row]=pa0.y; As[nb][q*4+2][row]=pa0.z; As[nb][q*4+3][row]=pa0.w;
              Ws[nb][q*4+0][row]=pw0.x; Ws[nb][q*4+1][row]=pw0.y; Ws[nb][q*4+2][row]=pw0.z; Ws[nb][q*4+3][row]=pw0.w; }
            { int f4 = tid + 256; int row = f4>>2, q = f4&3;
              As[nb][q*4+0][row]=pa1.x; As[nb][q*4+1][row]=pa1.y; As[nb][q*4+2][row]=pa1.z; As[nb][q*4+3][row]=pa1.w;
              Ws[nb][q*4+0][row]=pw1.x; Ws[nb][q*4+1][row]=pw1.y; Ws[nb][q*4+2][row]=pw1.z; Ws[nb][q*4+3][row]=pw1.w; }
            __syncthreads();
        }
    }
    float bv[8] = {0.f,0.f,0.f,0.f,0.f,0.f,0.f,0.f};
    if (bias){
        #pragma unroll
        for (int j = 0; j < 8; j++) bv[j] = bias[n0 + tn*8 + j];
    }
    #pragma unroll
    for (int i = 0; i < 8; i++){
        int m = m0 + tm*8 + i;
        float v[8];
        #pragma unroll
        for (int j = 0; j < 8; j++){
            v[j] = acc[i][j] + bv[j];
            if (act == 1) v[j] = geluf(v[j]);
        }
        float4* p = (float4*)(C + (size_t)m*Nq + n0 + tn*8);
        p[0] = make_float4(v[0], v[1], v[2], v[3]);
        p[1] = make_float4(v[4], v[5], v[6], v[7]);
    }
}

// ----- depthwise 3x3 conv + bias + SiLU, sliding-window; writes xcT AND u1t ---------------
__global__ void k_dwconv(const float* __restrict__ xz, const float* __restrict__ cw,
                         const float* __restrict__ cb, float* __restrict__ xcT,
                         float* __restrict__ u1t){
    int b = blockIdx.z, h = blockIdx.y, w0 = blockIdx.x<<5;
    int d = threadIdx.x;
    float wt[9];
    #pragma unroll
    for (int t2 = 0; t2 < 9; t2++) wt[t2] = __ldg(cw + d*9 + t2);
    float bi = __ldg(cb + d);
    int hm = h - 1, hp = h + 1;
    bool okm = (hm >= 0), okp = (hp < 128);
    const float* rowm = xz + ((size_t)(b*Ll + hm*128))*256 + d;
    const float* row0 = xz + ((size_t)(b*Ll + h *128))*256 + d;
    const float* rowp = xz + ((size_t)(b*Ll + hp*128))*256 + d;

    float a0[3], a1[3], a2[3];
    {
        int ww = w0 - 1;
        if (ww >= 0){
            a0[0] = okm ? rowm[(size_t)ww*256] : 0.f;
            a0[1] = row0[(size_t)ww*256];
            a0[2] = okp ? rowp[(size_t)ww*256] : 0.f;
        } else { a0[0]=a0[1]=a0[2]=0.f; }
    }
    {
        int ww = w0;
        a1[0] = okm ? rowm[(size_t)ww*256] : 0.f;
        a1[1] = row0[(size_t)ww*256];
        a1[2] = okp ? rowp[(size_t)ww*256] : 0.f;
    }
    for (int w = 0; w < 32; w++){
        int ww = w0 + w + 1;
        if (ww < 128){
            a2[0] = okm ? rowm[(size_t)ww*256] : 0.f;
            a2[1] = row0[(size_t)ww*256];
            a2[2] = okp ? rowp[(size_t)ww*256] : 0.f;
        } else { a2[0]=a2[1]=a2[2]=0.f; }
        float acc = bi;
        acc = fmaf(wt[0], a0[0], acc); acc = fmaf(wt[1], a1[0], acc); acc = fmaf(wt[2], a2[0], acc);
        acc = fmaf(wt[3], a0[1], acc); acc = fmaf(wt[4], a1[1], acc); acc = fmaf(wt[5], a2[1], acc);
        acc = fmaf(wt[6], a0[2], acc); acc = fmaf(wt[7], a1[2], acc); acc = fmaf(wt[8], a2[2], acc);
        acc = acc/(1.f + __expf(-acc));   // SiLU
        xcT[((size_t)(b*Ll + h*128 + w0 + w))*128 + d] = acc;
        u1t[((size_t)(b*Ll + (w0 + w)*128 + h))*128 + d] = acc;
        a0[0]=a1[0]; a0[1]=a1[1]; a0[2]=a1[2];
        a1[0]=a2[0]; a1[1]=a2[1]; a1[2]=a2[2];
    }
}

// -------- fused x_proj + scan pass 1 + (last block per (k,b)) chunk-combine ---------------
__global__ void k_xps(const float* __restrict__ xcT, const float* __restrict__ u1t,
                      const float* __restrict__ xpw,
                      const float* __restrict__ dtw, const float* __restrict__ dtb,
                      const float* __restrict__ Alogs,
                      float* __restrict__ bcbuf, float* __restrict__ dtsbuf,
                      float* __restrict__ sum, float* __restrict__ hinit){
    int k = blockIdx.y, b = blockIdx.z; int l0 = blockIdx.x*128;
    int chunk = blockIdx.x;
    __shared__ float Wp[36*128];
    __shared__ float UX[36*132];
    __shared__ __align__(16) float sB[LC*16];
    __shared__ __align__(16) float sdt[LC*4];
    __shared__ int is_last;
    int tid = threadIdx.x;
    const float* uptr = ((k&1) ? u1t : xcT) + (size_t)b*Ll*128;
    bool rev = (k >= 2);
    for (int e = tid; e < 36*128; e += 128) Wp[e] = xpw[(size_t)k*36*128 + e];

    int lt = tid & 31;
    int ct = tid >> 5;
    float acc[9][4] = {};

    for (int dc = 0; dc < 128; dc += 32){
        __syncthreads();
        #pragma unroll
        for (int rep = 0; rep < 8; rep++){
            int f4 = tid + rep*128;
            int l = f4>>3, dq = f4&7;
            int pos = l0 + l; int src = rev ? (Ll-1-pos) : pos;
            float4 uv = *(const float4*)(uptr + (size_t)src*128 + dc + dq*4);
            UX[(dq*4+0)*132 + l] = uv.x;
            UX[(dq*4+1)*132 + l] = uv.y;
            UX[(dq*4+2)*132 + l] = uv.z;
            UX[(dq*4+3)*132 + l] = uv.w;
        }
        __syncthreads();
        #pragma unroll 4
        for (int d2 = 0; d2 < 32; d2++){
            float4 uv = *(const float4*)&UX[d2*132 + lt*4];
            float wv[9];
            #pragma unroll
            for (int m = 0; m < 9; m++) wv[m] = Wp[(ct*9+m)*128 + dc + d2];
            #pragma unroll
            for (int m = 0; m < 9; m++){
                acc[m][0] = fmaf(wv[m], uv.x, acc[m][0]);
                acc[m][1] = fmaf(wv[m], uv.y, acc[m][1]);
                acc[m][2] = fmaf(wv[m], uv.z, acc[m][2]);
                acc[m][3] = fmaf(wv[m], uv.w, acc[m][3]);
            }
        }
    }
    __syncthreads();
    #pragma unroll
    for (int m = 0; m < 9; m++)
        *(float4*)&UX[(ct*9+m)*132 + lt*4] = *(float4*)acc[m];
    __syncthreads();
    size_t bcbase = ((size_t)(b*4+k)*Ll + l0)*32;
    for (int e = tid; e < 128*32; e += 128){
        int lo = e>>5, n = e&31;
        float v = UX[(4+n)*132 + lo];
        bcbuf[bcbase + (size_t)lo*32 + n] = v;
        if (n < 16) sB[lo*16 + n] = v;
    }
    size_t dtbase = ((size_t)(b*4+k)*Ll + l0)*4;
    for (int e = tid; e < 128*4; e += 128){
        int lo = e>>2, r = e&3;
        float v = UX[r*132 + lo];
        dtsbuf[dtbase + (size_t)lo*4 + r] = v;
        sdt[lo*4 + r] = v;
    }
    __syncthreads();

    // ---------------- scan pass 1 (local, h0 = 0) ----------------
    int d = tid;
    float Ahat[16];
    const float* Ap = Alogs + (size_t)(k*128+d)*16;
    #pragma unroll
    for (int n = 0; n < 16; n++) Ahat[n] = -expf(Ap[n]);
    bool geo = true;
    #pragma unroll
    for (int n = 0; n < 16; n++)
        geo = geo && (fabsf(Ahat[n] - (float)(n+1)*Ahat[0]) <= 1e-4f*fabsf(Ahat[n]));
    float4 wv = *(const float4*)(dtw + (size_t)k*512 + d*4);
    float bsv = dtb[k*128 + d];
    float h[16];
    #pragma unroll
    for (int n = 0; n < 16; n++) h[n] = 0.f;
    float S = 0.f;
    const float* ub = uptr + d;
    if (geo){
        float A0 = Ahat[0];
        #pragma unroll 2
        for (int t = 0; t < LC; t++){
            float4 q = *(const float4*)(sdt + t*4);
            float v = fmaf(wv.x,q.x, fmaf(wv.y,q.y, fmaf(wv.z,q.z, fmaf(wv.w,q.w, bsv))));
            float dv = (v > 20.f) ? v : __logf(1.f + __expf(v));
            int l = l0 + t; int ls = rev ? (Ll-1-l) : l;
            float uv = ub[(size_t)ls*128];
            float du = dv*uv;
            S += dv;
            float bb[16];
            *(float4*)(bb+0)  = *(const float4*)(sB + t*16 + 0);
            *(float4*)(bb+4)  = *(const float4*)(sB + t*16 + 4);
            *(float4*)(bb+8)  = *(const float4*)(sB + t*16 + 8);
            *(float4*)(bb+12) = *(const float4*)(sB + t*16 + 12);
            float p = __expf(dv*A0);
            float a = p;
            #pragma unroll
            for (int n = 0; n < 16; n++){
                h[n] = fmaf(a, h[n], du*bb[n]);
                a *= p;
            }
        }
    } else {
        #pragma unroll 2
        for (int t = 0; t < LC; t++){
            float4 q = *(const float4*)(sdt + t*4);
            float v = fmaf(wv.x,q.x, fmaf(wv.y,q.y, fmaf(wv.z,q.z, fmaf(wv.w,q.w, bsv))));
            float dv = (v > 20.f) ? v : __logf(1.f + __expf(v));
            int l = l0 + t; int ls = rev ? (Ll-1-l) : l;
            float uv = ub[(size_t)ls*128];
            float du = dv*uv;
            S += dv;
            float bb[16];
            *(float4*)(bb+0)  = *(const float4*)(sB + t*16 + 0);
            *(float4*)(bb+4)  = *(const float4*)(sB + t*16 + 4);
            *(float4*)(bb+8)  = *(const float4*)(sB + t*16 + 8);
            *(float4*)(bb+12) = *(const float4*)(sB + t*16 + 12);
            #pragma unroll
            for (int n = 0; n < 16; n++){
                float a = __expf(dv*Ahat[n]);
                h[n] = fmaf(a, h[n], du*bb[n]);
            }
        }
    }
    float* sp = sum + (((size_t)((b*4+k)*NC + chunk)*128 + d)*32);
    #pragma unroll
    for (int n = 0; n < 16; n++){ sp[n] = __expf(S*Ahat[n]); sp[16+n] = h[n]; }

    // ---------------- last block per (k,b): sequential chunk combine ----------------
    __threadfence();
    if (tid == 0){
        int old = atomicAdd(&g_cnt[b*4+k], 1);
        is_last = (old == 127) ? 1 : 0;
        if (old == 127) g_cnt[b*4+k] = 0;
    }
    __syncthreads();
    if (is_last){
        __threadfence();
        int kb = b*4+k;
        float hc[16];
        #pragma unroll
        for (int n = 0; n < 16; n++) hc[n] = 0.f;
        size_t stride = 128*32;
        size_t b0 = ((size_t)kb*NC*128 + tid)*32;
        float* hpout = hinit + ((size_t)kb*NC*128 + tid)*16;
        const float4* spc = (const float4*)(sum + b0);
        float4 P0=spc[0], P1=spc[1], P2=spc[2], P3=spc[3];
        float4 E0=spc[4], E1=spc[5], E2=spc[6], E3=spc[7];
        for (int c = 0; c < NC; c++){
            float4 nP0, nP1, nP2, nP3, nE0, nE1, nE2, nE3;
            if (c + 1 < NC){
                const float4* spn = (const float4*)(sum + b0 + (size_t)(c+1)*stride);
                nP0=spn[0]; nP1=spn[1]; nP2=spn[2]; nP3=spn[3];
                nE0=spn[4]; nE1=spn[5]; nE2=spn[6]; nE3=spn[7];
            }
            float4* op = (float4*)(hpout + (size_t)c*128*16);
            op[0] = make_float4(hc[0],hc[1],hc[2],hc[3]);
            op[1] = make_float4(hc[4],hc[5],hc[6],hc[7]);
            op[2] = make_float4(hc[8],hc[9],hc[10],hc[11]);
            op[3] = make_float4(hc[12],hc[13],hc[14],hc[15]);
            hc[0]=fmaf(P0.x,hc[0],E0.x); hc[1]=fmaf(P0.y,hc[1],E0.y);
            hc[2]=fmaf(P0.z,hc[2],E0.z); hc[3]=fmaf(P0.w,hc[3],E0.w);
            hc[4]=fmaf(P1.x,hc[4],E1.x); hc[5]=fmaf(P1.y,hc[5],E1.y);
            hc[6]=fmaf(P1.z,hc[6],E1.z); hc[7]=fmaf(P1.w,hc[7],E1.w);
            hc[8]=fmaf(P2.x,hc[8],E2.x); hc[9]=fmaf(P2.y,hc[9],E2.y);
            hc[10]=fmaf(P2.z,hc[10],E2.z); hc[11]=fmaf(P2.w,hc[11],E2.w);
            hc[12]=fmaf(P3.x,hc[12],E3.x); hc[13]=fmaf(P3.y,hc[13],E3.y);
            hc[14]=fmaf(P3.z,hc[14],E3.z); hc[15]=fmaf(P3.w,hc[15],E3.w);
            P0=nP0; P1=nP1; P2=nP2; P3=nP3;
            E0=nE0; E1=nE1; E2=nE2; E3=nE3;
        }
    }
}

// -------------------- scan pass 3: full scan per chunk with true init, emit y ------------
__global__ void k_scan3(const float* __restrict__ xcT, const float* __restrict__ u1t,
                        const float* __restrict__ dts, const float* __restrict__ bc,
                        const float* __restrict__ dtw, const float* __restrict__ dtb,
                        const float* __restrict__ Alogs, const float* __restrict__ Ds,
                        const float* __restrict__ hinit, float* __restrict__ ys){
    int chunk = blockIdx.x, k = blockIdx.y, b = blockIdx.z;
    int d = threadIdx.x;
    __shared__ __align__(16) float sBC[LC*32];
    __shared__ __align__(16) float sdt[LC*4];
    int l0 = chunk*LC;
    const float4* bcp4 = (const float4*)(bc + ((size_t)(b*4+k)*Ll + l0)*32);
    for (int e = d; e < LC*8; e += 128) ((float4*)sBC)[e] = bcp4[e];
    ((float4*)sdt)[d] = ((const float4*)(dts + ((size_t)(b*4+k)*Ll + l0)*4))[d];
    __syncthreads();
    float Ahat[16];
    const float* Ap = Alogs + (size_t)(k*128+d)*16;
    #pragma unroll
    for (int n = 0; n < 16; n++) Ahat[n] = -expf(Ap[n]);
    bool geo = true;
    #pragma unroll
    for (int n = 0; n < 16; n++)
        geo = geo && (fabsf(Ahat[n] - (float)(n+1)*Ahat[0]) <= 1e-4f*fabsf(Ahat[n]));
    float4 wv = *(const float4*)(dtw + (size_t)k*512 + d*4);
    float bsv = dtb[k*128 + d];
    float Dv = Ds[k*128 + d];
    const float* hi = hinit + ((size_t)((b*4+k)*NC + chunk)*128 + d)*16;
    const float* ub = ((k&1) ? u1t : xcT) + (size_t)b*Ll*128 + d;
    float* yp = ys + ((size_t)(b*4+k)*Ll + l0)*128 + d;
    bool rev = (k >= 2);
    if (geo){
        float A0 = Ahat[0];
        ull h2[8];
        {
            const ulonglong2* hi2 = (const ulonglong2*)hi;
            ulonglong2 t0 = hi2[0], t1 = hi2[1], t2 = hi2[2], t3 = hi2[3];
            h2[0]=t0.x; h2[1]=t0.y; h2[2]=t1.x; h2[3]=t1.y;
            h2[4]=t2.x; h2[5]=t2.y; h2[6]=t3.x; h2[7]=t3.y;
        }
        #pragma unroll 2
        for (int t = 0; t < LC; t++){
            float4 q = *(const float4*)(sdt + t*4);
            float v = fmaf(wv.x,q.x, fmaf(wv.y,q.y, fmaf(wv.z,q.z, fmaf(wv.w,q.w, bsv))));
            float dv = (v > 20.f) ? v : __logf(1.f + __expf(v));
            int l = l0 + t; int ls = rev ? (Ll-1-l) : l;
            float uv = ub[(size_t)ls*128];
            float du = dv*uv;
            float p = __expf(dv*A0);
            float pq = p*p;
            ull du2 = pack2(du, du);
            ull pk  = pack2(pq, pq);
            ull a0 = pack2(p, pq);
            ull a1 = mul2(a0, pk);
            ull a2 = mul2(a1, pk);
            ull a3 = mul2(a2, pk);
            ull a4 = mul2(a3, pk);
            ull a5 = mul2(a4, pk);
            ull a6 = mul2(a5, pk);
            ull a7 = mul2(a6, pk);
            const ulonglong2* rb = (const ulonglong2*)(sBC + t*32);
            ulonglong2 b01=rb[0], b23=rb[1], b45=rb[2], b67=rb[3];
            ulonglong2 c01=rb[4], c23=rb[5], c45=rb[6], c67=rb[7];
            h2[0] = fma2(a0, h2[0], mul2(du2, b01.x));
            h2[1] = fma2(a1, h2[1], mul2(du2, b01.y));
            h2[2] = fma2(a2, h2[2], mul2(du2, b23.x));
            h2[3] = fma2(a3, h2[3], mul2(du2, b23.y));
            h2[4] = fma2(a4, h2[4], mul2(du2, b45.x));
            h2[5] = fma2(a5, h2[5], mul2(du2, b45.y));
            h2[6] = fma2(a6, h2[6], mul2(du2, b67.x));
            h2[7] = fma2(a7, h2[7], mul2(du2, b67.y));
            ull y0 = 0ull, y1 = 0ull;
            y0 = fma2(h2[0], c01.x, y0); y1 = fma2(h2[1], c01.y, y1);
            y0 = fma2(h2[2], c23.x, y0); y1 = fma2(h2[3], c23.y, y1);
            y0 = fma2(h2[4], c45.x, y0); y1 = fma2(h2[5], c45.y, y1);
            y0 = fma2(h2[6], c67.x, y0); y1 = fma2(h2[7], c67.y, y1);
            float2 ya = unpack2(y0);
            float2 yb = unpack2(y1);
            yp[(size_t)t*128] = ((ya.x+ya.y)+(yb.x+yb.y)) + Dv*uv;
        }
    } else {
        float h[16];
        #pragma unroll
        for (int n = 0; n < 16; n++) h[n] = hi[n];
        #pragma unroll 2
        for (int t = 0; t < LC; t++){
            float4 q = *(const float4*)(sdt + t*4);
            float v = fmaf(wv.x,q.x, fmaf(wv.y,q.y, fmaf(wv.z,q.z, fmaf(wv.w,q.w, bsv))));
            float dv = (v > 20.f) ? v : __logf(1.f + __expf(v));
            int l = l0 + t; int ls = rev ? (Ll-1-l) : l;
            float uv = ub[(size_t)ls*128];
            float du = dv*uv;
            float bb[16], cc[16];
            const float4* rb = (const float4*)(sBC + t*32);
            *(float4*)(bb+0)=rb[0]; *(float4*)(bb+4)=rb[1]; *(float4*)(bb+8)=rb[2]; *(float4*)(bb+12)=rb[3];
            *(float4*)(cc+0)=rb[4]; *(float4*)(cc+4)=rb[5]; *(float4*)(cc+8)=rb[6]; *(float4*)(cc+12)=rb[7];
            float y0 = 0.f, y1 = 0.f;
            #pragma unroll
            for (int n = 0; n < 16; n += 2){
                float e0 = __expf(dv*Ahat[n]);
                float e1 = __expf(dv*Ahat[n+1]);
                h[n]   = fmaf(e0, h[n],   du*bb[n]);
                h[n+1] = fmaf(e1, h[n+1], du*bb[n+1]);
                y0 = fmaf(h[n],   cc[n],   y0);
                y1 = fmaf(h[n+1], cc[n+1], y1);
            }
            yp[(size_t)t*128] = y0 + y1 + Dv*uv;
        }
    }
}

// ---- fused cross-merge + out_norm(LN 128) * silu(z); warp-per-row, shfl-only -------------
__global__ void k_yo(const float* __restrict__ ys, const float* __restrict__ xz,
                     const float* __restrict__ g, const float* __restrict__ bb,
                     float* __restrict__ yo){
    int b = blockIdx.y;
    int warp = threadIdx.x>>5, lane = threadIdx.x&31;
    int l = blockIdx.x*8 + warp;
    int lT = ((l & 127) << 7) | (l >> 7);
    size_t st = (size_t)Ll*128;
    size_t base = (size_t)b*4*st;
    int d0 = lane*4;
    float4 v0 = *(const float4*)(ys + base        + (size_t)l*128         + d0);
    float4 v2 = *(const float4*)(ys + base + 2*st + (size_t)(Ll-1-l)*128  + d0);
    float4 v1 = *(const float4*)(ys + base + 1*st + (size_t)lT*128        + d0);
    float4 v3 = *(const float4*)(ys + base + 3*st + (size_t)(Ll-1-lT)*128 + d0);
    float4 v;
    v.x = (v0.x+v2.x)+(v1.x+v3.x);
    v.y = (v0.y+v2.y)+(v1.y+v3.y);
    v.z = (v0.z+v2.z)+(v1.z+v3.z);
    v.w = (v0.w+v2.w)+(v1.w+v3.w);
    float s  = (v.x+v.y)+(v.z+v.w);
    float s2 = (v.x*v.x+v.y*v.y)+(v.z*v.z+v.w*v.w);
    #pragma unroll
    for (int o = 16; o; o >>= 1){ s += __shfl_xor_sync(~0u, s, o); s2 += __shfl_xor_sync(~0u, s2, o); }
    float mean = s*(1.f/128.f);
    float rstd = rsqrtf(s2*(1.f/128.f) - mean*mean + 1e-5f);
    float4 gv = *(const float4*)(g + d0);
    float4 bv = *(const float4*)(bb + d0);
    float4 z  = *(const float4*)(xz + ((size_t)(b*Ll) + l)*256 + 128 + d0);
    float4 ov;
    ov.x = ((v.x-mean)*rstd*gv.x + bv.x) * (z.x/(1.f + __expf(-z.x)));
    ov.y = ((v.y-mean)*rstd*gv.y + bv.y) * (z.y/(1.f + __expf(-z.y)));
    ov.z = ((v.z-mean)*rstd*gv.z + bv.z) * (z.z/(1.f + __expf(-z.z)));
    ov.w = ((v.w-mean)*rstd*gv.w + bv.w) * (z.w/(1.f + __expf(-z.w)));
    *(float4*)(yo + ((size_t)(b*Ll) + l)*128 + d0) = ov;
}

// ------- head conv1: 64->32, 3x3, leaky; full-row blocks, 4w x 4oc per thread -------------
__global__ void __launch_bounds__(256) k_conv1(const float* __restrict__ t,
                                               const float* __restrict__ w1,
                                               float* __restrict__ o1){
    extern __shared__ float st[];
    int b = blockIdx.y, h = blockIdx.x;
    int tid = threadIdx.x;
    for (int e = tid; e < 3*130*16; e += 256){
        int c4 = e & 15;
        int wi = (e>>4) % 130;
        int r  = (e>>4) / 130;
        int hh = h + r - 1, ww = wi - 1;
        float4 v = make_float4(0.f,0.f,0.f,0.f);
        if ((unsigned)hh < 128u && (unsigned)ww < 128u)
            v = *(const float4*)(t + ((size_t)(b*Ll) + hh*128 + ww)*64 + c4*4);
        st[((size_t)r*64 + c4*4+0)*132 + wi] = v.x;
        st[((size_t)r*64 + c4*4+1)*132 + wi] = v.y;
        st[((size_t)r*64 + c4*4+2)*132 + wi] = v.z;
        st[((size_t)r*64 + c4*4+3)*132 + wi] = v.w;
    }
    __syncthreads();
    int wq = tid & 31;
    int og = tid >> 5;
    int wbase = wq*4;
    float acc[4][4] = {};
    #pragma unroll
    for (int kh = 0; kh < 3; kh++){
        for (int ic = 0; ic < 64; ic++){
            float in[8];
            const float* rowp = st + ((size_t)kh*64 + ic)*132;
            *(float4*)(in+0) = *(const float4*)(rowp + wbase);
            *(float4*)(in+4) = *(const float4*)(rowp + wbase + 4);
            #pragma unroll
            for (int kw = 0; kw < 3; kw++){
                float wt[4];
                #pragma unroll
                for (int j = 0; j < 4; j++)
                    wt[j] = __ldg(w1 + ((size_t)((og*4+j)*64 + ic))*9 + kh*3 + kw);
                #pragma unroll
                for (int j = 0; j < 4; j++){
                    acc[0][j] = fmaf(wt[j], in[0+kw], acc[0][j]);
                    acc[1][j] = fmaf(wt[j], in[1+kw], acc[1][j]);
                    acc[2][j] = fmaf(wt[j], in[2+kw], acc[2][j]);
                    acc[3][j] = fmaf(wt[j], in[3+kw], acc[3][j]);
                }
            }
        }
    }
    #pragma unroll
    for (int j = 0; j < 4; j++){
        #pragma unroll
        for (int w2 = 0; w2 < 4; w2++){
            float v = acc[w2][j];
            v = (v >= 0.f) ? v : 0.01f*v;
            o1[((size_t)(b*32 + og*4 + j))*Ll + h*128 + wbase + w2] = v;
        }
    }
}

// ------- head conv2: 32->1, 3x3, + img, sigmoid; full-row blocks, smem-staged -------------
__global__ void __launch_bounds__(128) k_conv2(const float* __restrict__ o1,
                                               const float* __restrict__ w2,
                                               const float* __restrict__ img,
                                               float* __restrict__ out){
    extern __shared__ float sc[];
    int b = blockIdx.y, h = blockIdx.x;
    int tid = threadIdx.x;
    for (int e = tid; e < 32*3*130; e += 128){
        int s = e % 130;
        int rc = e / 130;
        int r = rc % 3, ic = rc / 3;
        int hh = h + r - 1, ww = s - 1;
        float v = 0.f;
        if ((unsigned)hh < 128u && (unsigned)ww < 128u)
            v = o1[((size_t)(b*32 + ic))*Ll + hh*128 + ww];
        sc[((size_t)ic*3 + r)*132 + s] = v;
    }
    __syncthreads();
    int w = tid;
    float acc = 0.f;
    for (int ic = 0; ic < 32; ic++){
        #pragma unroll
        for (int kh = 0; kh < 3; kh++){
            const float* rowp = sc + ((size_t)ic*3 + kh)*132;
            float w0 = __ldg(w2 + ic*9 + kh*3 + 0);
            float w1v = __ldg(w2 + ic*9 + kh*3 + 1);
            float w2v = __ldg(w2 + ic*9 + kh*3 + 2);
            acc = fmaf(w0,  rowp[w+0], acc);
            acc = fmaf(w1v, rowp[w+1], acc);
            acc = fmaf(w2v, rowp[w+2], acc);
        }
    }
    int idx = (b<<14) + h*128 + w;
    float o = acc + img[idx];
    out[idx] = 1.f/(1.f + expf(-o));
}

// -------------------- launch --------------------
extern "C" void kernel_launch(void* const* d_in, const int* in_sizes, int n_in,
                              void* d_out, int out_size){
    const float* inp_img   = (const float*)d_in[0];
    const float* x         = (const float*)d_in[1];
    const float* y         = (const float*)d_in[2];
    const float* reduce_w  = (const float*)d_in[3];
    const float* patch_w   = (const float*)d_in[4];
    const float* patch_g   = (const float*)d_in[5];
    const float* patch_b   = (const float*)d_in[6];
    const float* ln1_g     = (const float*)d_in[7];
    const float* ln1_b     = (const float*)d_in[8];
    const float* in_proj_w = (const float*)d_in[9];
    const float* conv_w    = (const float*)d_in[10];
    const float* conv_b    = (const float*)d_in[11];
    const float* x_proj_w  = (const float*)d_in[12];
    const float* dt_proj_w = (const float*)d_in[13];
    const float* dt_proj_b = (const float*)d_in[14];
    const float* A_logs    = (const float*)d_in[15];
    const float* Ds_p      = (const float*)d_in[16];
    const float* out_norm_g= (const float*)d_in[17];
    const float* out_norm_b= (const float*)d_in[18];
    const float* out_proj_w= (const float*)d_in[19];
    const float* ln2_g     = (const float*)d_in[20];
    const float* ln2_b     = (const float*)d_in[21];
    const float* fc1_w     = (const float*)d_in[22];
    const float* fc1_b     = (const float*)d_in[23];
    const float* fc2_w     = (const float*)d_in[24];
    const float* fc2_b     = (const float*)d_in[25];
    const float* out1_w    = (const float*)d_in[26];
    const float* out2_w    = (const float*)d_in[27];

    float* out = (float*)d_out;
    float* f   = out + Bn*Ll;   // second output: f at offset 32768

    float *t, *h, *xz, *xcT, *u1t, *bcp, *dtsb, *ysb, *yob, *o1b, *sumb, *hib;
    cudaGetSymbolAddress((void**)&t,    g_t);
    cudaGetSymbolAddress((void**)&h,    g_h);
    cudaGetSymbolAddress((void**)&xz,   g_xz);
    cudaGetSymbolAddress((void**)&xcT,  g_xcT);
    cudaGetSymbolAddress((void**)&u1t,  g_u1t);
    cudaGetSymbolAddress((void**)&bcp,  g_bc);
    cudaGetSymbolAddress((void**)&dtsb, g_dts);
    cudaGetSymbolAddress((void**)&ysb,  g_ys);
    cudaGetSymbolAddress((void**)&yob,  g_yo);
    cudaGetSymbolAddress((void**)&o1b,  g_o1);
    cudaGetSymbolAddress((void**)&sumb, g_sum);
    cudaGetSymbolAddress((void**)&hib,  g_hinit);

    const int C1_SMEM = 3*64*132*4;    // 101376 bytes
    const int C2_SMEM = 32*3*132*4;    // 50688 bytes
    cudaFuncSetAttribute(k_conv1, cudaFuncAttributeMaxDynamicSharedMemorySize, C1_SMEM);
    cudaFuncSetAttribute(k_conv2, cudaFuncAttributeMaxDynamicSharedMemorySize, C2_SMEM);

    const int M = Bn*Ll;  // 32768

    k_reduce<<<dim3(512,2), 256>>>(x, y, reduce_w, f);
    k_patch <<<dim3(512,2), 256>>>(f, patch_w, h);
    k_ln64  <<<M/8, 256>>>(h, t, patch_g, patch_b);

    for (int i = 0; i < NB; i++){
        const float* dtw_i = dt_proj_w + (size_t)i*Kk*DI*4;
        const float* dtb_i = dt_proj_b + (size_t)i*Kk*DI;
        const float* Al_i  = A_logs   + (size_t)i*Kk*DI*16;
        if (i == 0)
            k_ln64 <<<M/8, 256>>>(t, h, ln1_g, ln1_b);
        k_gemm128<<<dim3(2,256), 256>>>(h, in_proj_w + (size_t)i*256*64, nullptr, xz,
                                        M, 256, 64, 0);
        k_dwconv <<<dim3(4,128,2), 128>>>(xz, conv_w + (size_t)i*DI*9, conv_b + i*DI, xcT, u1t);
        k_xps    <<<dim3(128,4,2), 128>>>(xcT, u1t, x_proj_w + (size_t)i*Kk*36*DI,
                                          dtw_i, dtb_i, Al_i, bcp, dtsb, sumb, hib);
        k_scan3  <<<dim3(NC,Kk,Bn), 128>>>(xcT, u1t, dtsb, bcp, dtw_i, dtb_i, Al_i,
                                           Ds_p + (size_t)i*Kk*DI, hib, ysb);
        k_yo     <<<dim3(2048,Bn), 256>>>(ysb, xz, out_norm_g + i*128, out_norm_b + i*128, yob);
        // out_proj accumulate into t, fused LN2 -> h
        k_gemm   <<<dim3(1,256), 256>>>(yob, out_proj_w + (size_t)i*64*128, nullptr, t,
                                        M, 64, 128, 0, 1,
                                        ln2_g + i*64, ln2_b + i*64, h);
        // MLP: fc1 (+GELU) into xz, fc2 accumulate into t with fused next-LN1 -> h
        k_gemm128<<<dim3(2,256), 256>>>(h, fc1_w + (size_t)i*256*64, fc1_b + i*256, xz,
                                        M, 256, 64, 1);
        if (i < NB-1)
            k_gemm <<<dim3(1,256), 256>>>(xz, fc2_w + (size_t)i*64*256, fc2_b + i*64, t,
                                          M, 64, 256, 0, 1,
                                          ln1_g + (i+1)*64, ln1_b + (i+1)*64, h);
        else
            k_gemm <<<dim3(1,256), 256>>>(xz, fc2_w + (size_t)i*64*256, fc2_b + i*64, t,
                                          M, 64, 256, 0, 1,
                                          nullptr, nullptr, nullptr);
    }

    k_conv1<<<dim3(128,2), 256, C1_SMEM>>>(t, out1_w, o1b);
    k_conv2<<<dim3(128,2), 128, C2_SMEM>>>(o1b, out2_w, inp_img, out);
}

// round 15
// speedup vs baseline: 1.7764x; 1.7764x over previous
#include <cuda_runtime.h>
#include <math.h>

#define Bn 2
#define Ll 16384
#define DI 128
#define Kk 4
#define NB 4
#define NC 128          // chunks per sequence
#define LC 128          // chunk length

// -------------------- scratch (device globals; no allocation) --------------------
__device__ float g_t  [Bn*Ll*64];        // residual stream (b,l,64)
__device__ float g_h  [Bn*Ll*64];        // LN scratch (b,l,64)
__device__ float g_xz [Bn*Ll*256];       // in_proj out / MLP hidden (b,l,256)
__device__ float g_xcT[Bn*Ll*DI];        // conv+silu out, NHWC (b,l,d)
__device__ float g_u1t[Bn*Ll*DI];        // wh-order (b, w*128+h, d)
__device__ float g_bc [Bn*Kk*Ll*32];     // B(16)+C(16) per (b,k,l)
__device__ float g_dts[Bn*Kk*Ll*4];      // raw dt-rank values per (b,k,l)
__device__ float g_ys [(size_t)Bn*Kk*Ll*DI];   // (b,k,l,d)
__device__ float g_yo [Bn*Ll*DI];        // gated+LN (b,l,d)
__device__ float g_o1 [Bn*32*Ll];        // head conv1 out (b,32,l)
__device__ float g_sum  [Bn*Kk*NC*DI*32];  // per-chunk {P[16], hEnd[16]}
__device__ float g_hinit[Bn*Kk*NC*DI*16];  // per-chunk init state

__device__ __forceinline__ float geluf(float v){
    return 0.5f*v*(1.f + erff(v*0.70710678118654752f));
}

// -------------------- stem: f = 1x1 conv over concat(x,y) --------------------
__global__ void k_reduce(const float* __restrict__ x, const float* __restrict__ y,
                         const float* __restrict__ rw, float* __restrict__ f){
    __shared__ float sx[128][33];
    __shared__ float so[64][33];
    int b = blockIdx.y; int l0 = blockIdx.x*32;
    int tid = threadIdx.x;
    for (int e = tid; e < 128*32; e += 256){
        int c = e>>5, li = e&31;
        sx[c][li] = (c < 64) ? x[((size_t)(b*64+c))*Ll + l0+li]
                             : y[((size_t)(b*64+c-64))*Ll + l0+li];
    }
    __syncthreads();
    int o = tid>>2, lb = (tid&3)*8;
    float acc[8] = {0.f,0.f,0.f,0.f,0.f,0.f,0.f,0.f};
    for (int c = 0; c < 128; c++){
        float w = __ldg(rw + o*128 + c);
        #pragma unroll
        for (int j = 0; j < 8; j++) acc[j] += w*sx[c][lb+j];
    }
    #pragma unroll
    for (int j = 0; j < 8; j++) so[o][lb+j] = acc[j];
    __syncthreads();
    for (int e = tid; e < 64*32; e += 256){
        int oo = e>>5, li = e&31;
        f[((size_t)(b*64+oo))*Ll + l0+li] = so[oo][li];
    }
}

// -------------------- patch embed 1x1 conv (reads f), writes (b,l,64) --------------------
__global__ void k_patch(const float* __restrict__ f, const float* __restrict__ pw,
                        float* __restrict__ out){
    __shared__ float sx[64][33];
    __shared__ float so[64][33];
    int b = blockIdx.y; int l0 = blockIdx.x*32;
    int tid = threadIdx.x;
    for (int e = tid; e < 64*32; e += 256){
        int c = e>>5, li = e&31;
        sx[c][li] = f[((size_t)(b*64+c))*Ll + l0+li];
    }
    __syncthreads();
    int o = tid>>2, lb = (tid&3)*8;
    float acc[8] = {0.f,0.f,0.f,0.f,0.f,0.f,0.f,0.f};
    for (int c = 0; c < 64; c++){
        float w = __ldg(pw + o*64 + c);
        #pragma unroll
        for (int j = 0; j < 8; j++) acc[j] += w*sx[c][lb+j];
    }
    #pragma unroll
    for (int j = 0; j < 8; j++) so[o][lb+j] = acc[j];
    __syncthreads();
    for (int e = tid; e < 64*32; e += 256){
        int o2 = e&63, li = e>>6;
        out[((size_t)(b*Ll) + l0 + li)*64 + o2] = so[o2][li];
    }
}

// ------------- LayerNorm over last dim of 64; warp-per-row, shfl-only --------------------
__global__ void k_ln64(const float* __restrict__ in, float* __restrict__ out,
                       const float* __restrict__ g, const float* __restrict__ bb){
    int warp = threadIdx.x>>5, lane = threadIdx.x&31;
    size_t row = (size_t)blockIdx.x*8 + warp;
    float2 v = *(const float2*)(in + row*64 + lane*2);
    float s = v.x + v.y, s2 = v.x*v.x + v.y*v.y;
    #pragma unroll
    for (int o = 16; o; o >>= 1){ s += __shfl_xor_sync(~0u, s, o); s2 += __shfl_xor_sync(~0u, s2, o); }
    float mean = s*(1.f/64.f);
    float rstd = rsqrtf(s2*(1.f/64.f) - mean*mean + 1e-5f);
    float2 gg = *(const float2*)(g + lane*2);
    float2 bv = *(const float2*)(bb + lane*2);
    float2 ov;
    ov.x = (v.x-mean)*rstd*gg.x + bv.x;
    ov.y = (v.y-mean)*rstd*gg.y + bv.y;
    *(float2*)(out + row*64 + lane*2) = ov;
}

// ------ GEMM 128x64 tile, 8x4/thread, double-buffered; optional fused row-LN epilogue -----
__global__ void k_gemm(const float* __restrict__ A, const float* __restrict__ Wm,
                       const float* __restrict__ bias, float* __restrict__ C,
                       int M, int Nq, int Kd, int act, int accum,
                       const float* __restrict__ lng, const float* __restrict__ lnb,
                       float* __restrict__ lnout){
    __shared__ float As[2][16][132];
    __shared__ float Ws[2][16][68];
    int m0 = blockIdx.y<<7, n0 = blockIdx.x<<6;
    int tid = threadIdx.x;
    int tm = tid>>4, tn = tid&15;
    float acc[8][4] = {};

    {
        #pragma unroll
        for (int rep = 0; rep < 2; rep++){
            int f4 = tid + rep*256;
            int row = f4>>2, q = f4&3;
            float4 av = *(const float4*)(A + (size_t)(m0+row)*Kd + 0 + q*4);
            As[0][q*4+0][row]=av.x; As[0][q*4+1][row]=av.y; As[0][q*4+2][row]=av.z; As[0][q*4+3][row]=av.w;
        }
        int row = tid>>2, q = tid&3;
        float4 wv = *(const float4*)(Wm + (size_t)(n0+row)*Kd + 0 + q*4);
        Ws[0][q*4+0][row]=wv.x; Ws[0][q*4+1][row]=wv.y; Ws[0][q*4+2][row]=wv.z; Ws[0][q*4+3][row]=wv.w;
    }
    __syncthreads();

    int buf = 0;
    for (int kk = 0; kk < Kd; kk += 16, buf ^= 1){
        float4 pa0, pa1, pw;
        bool more = (kk + 16) < Kd;
        if (more){
            { int row = tid>>2, q = tid&3;
              pa0 = *(const float4*)(A + (size_t)(m0+row)*Kd + kk+16 + q*4); }
            { int f4 = tid + 256; int row = f4>>2, q = f4&3;
              pa1 = *(const float4*)(A + (size_t)(m0+row)*Kd + kk+16 + q*4); }
            { int row = tid>>2, q = tid&3;
              pw = *(const float4*)(Wm + (size_t)(n0+row)*Kd + kk+16 + q*4); }
        }
        #pragma unroll
        for (int k = 0; k < 16; k++){
            float a[8], w[4];
            *(float4*)(a+0) = *(const float4*)&As[buf][k][tm*8+0];
            *(float4*)(a+4) = *(const float4*)&As[buf][k][tm*8+4];
            *(float4*)(w+0) = *(const float4*)&Ws[buf][k][tn*4];
            #pragma unroll
            for (int i = 0; i < 8; i++){
                acc[i][0] = fmaf(a[i], w[0], acc[i][0]);
                acc[i][1] = fmaf(a[i], w[1], acc[i][1]);
                acc[i][2] = fmaf(a[i], w[2], acc[i][2]);
                acc[i][3] = fmaf(a[i], w[3], acc[i][3]);
            }
        }
        if (more){
            int nb = buf^1;
            { int row = tid>>2, q = tid&3;
              As[nb][q*4+0][row]=pa0.x; As[nb][q*4+1][row]=pa0.y; As[nb][q*4+2][row]=pa0.z; As[nb][q*4+3][row]=pa0.w; }
            { int f4 = tid + 256; int row = f4>>2, q = f4&3;
              As[nb][q*4+0][row]=pa1.x; As[nb][q*4+1][row]=pa1.y; As[nb][q*4+2][row]=pa1.z; As[nb][q*4+3][row]=pa1.w; }
            { int row = tid>>2, q = tid&3;
              Ws[nb][q*4+0][row]=pw.x; Ws[nb][q*4+1][row]=pw.y; Ws[nb][q*4+2][row]=pw.z; Ws[nb][q*4+3][row]=pw.w; }
            __syncthreads();
        }
    }
    float bv[4] = {0.f,0.f,0.f,0.f};
    if (bias){
        #pragma unroll
        for (int j = 0; j < 4; j++) bv[j] = bias[n0 + tn*4 + j];
    }
    float gv[4], gb[4];
    if (lng){
        #pragma unroll
        for (int j = 0; j < 4; j++){ gv[j] = lng[tn*4 + j]; gb[j] = lnb[tn*4 + j]; }
    }
    #pragma unroll
    for (int i = 0; i < 8; i++){
        int m = m0 + tm*8 + i;
        float4* p = (float4*)(C + (size_t)m*Nq + n0 + tn*4);
        float v0 = acc[i][0]+bv[0], v1 = acc[i][1]+bv[1], v2 = acc[i][2]+bv[2], v3 = acc[i][3]+bv[3];
        if (act == 1){ v0=geluf(v0); v1=geluf(v1); v2=geluf(v2); v3=geluf(v3); }
        if (accum){ float4 old = *p; v0+=old.x; v1+=old.y; v2+=old.z; v3+=old.w; }
        *p = make_float4(v0, v1, v2, v3);
        if (lng){
            float rs  = v0+v1+v2+v3;
            float rs2 = v0*v0+v1*v1+v2*v2+v3*v3;
            #pragma unroll
            for (int o = 1; o < 16; o <<= 1){
                rs  += __shfl_xor_sync(~0u, rs,  o);
                rs2 += __shfl_xor_sync(~0u, rs2, o);
            }
            float mean = rs*(1.f/64.f);
            float rstd = rsqrtf(rs2*(1.f/64.f) - mean*mean + 1e-5f);
            float4 hv;
            hv.x = (v0-mean)*rstd*gv[0] + gb[0];
            hv.y = (v1-mean)*rstd*gv[1] + gb[1];
            hv.z = (v2-mean)*rstd*gv[2] + gb[2];
            hv.w = (v3-mean)*rstd*gv[3] + gb[3];
            *(float4*)(lnout + (size_t)m*64 + tn*4) = hv;
        }
    }
}

// ------ GEMM 128x128 tile, 8x8 per thread, double-buffered (N multiple of 128) -----------
__global__ void __launch_bounds__(256) k_gemm128(
                       const float* __restrict__ A, const float* __restrict__ Wm,
                       const float* __restrict__ bias, float* __restrict__ C,
                       int M, int Nq, int Kd, int act){
    __shared__ float As[2][16][132];
    __shared__ float Ws[2][16][132];
    int m0 = blockIdx.y<<7, n0 = blockIdx.x<<7;
    int tid = threadIdx.x;
    int tm = tid>>4, tn = tid&15;
    float acc[8][8] = {};

    {
        #pragma unroll
        for (int rep = 0; rep < 2; rep++){
            int f4 = tid + rep*256;
            int row = f4>>2, q = f4&3;
            float4 av = *(const float4*)(A + (size_t)(m0+row)*Kd + 0 + q*4);
            As[0][q*4+0][row]=av.x; As[0][q*4+1][row]=av.y; As[0][q*4+2][row]=av.z; As[0][q*4+3][row]=av.w;
            float4 wv = *(const float4*)(Wm + (size_t)(n0+row)*Kd + 0 + q*4);
            Ws[0][q*4+0][row]=wv.x; Ws[0][q*4+1][row]=wv.y; Ws[0][q*4+2][row]=wv.z; Ws[0][q*4+3][row]=wv.w;
        }
    }
    __syncthreads();

    int buf = 0;
    for (int kk = 0; kk < Kd; kk += 16, buf ^= 1){
        float4 pa0, pa1, pw0, pw1;
        bool more = (kk + 16) < Kd;
        if (more){
            { int row = tid>>2, q = tid&3;
              pa0 = *(const float4*)(A  + (size_t)(m0+row)*Kd + kk+16 + q*4);
              pw0 = *(const float4*)(Wm + (size_t)(n0+row)*Kd + kk+16 + q*4); }
            { int f4 = tid + 256; int row = f4>>2, q = f4&3;
              pa1 = *(const float4*)(A  + (size_t)(m0+row)*Kd + kk+16 + q*4);
              pw1 = *(const float4*)(Wm + (size_t)(n0+row)*Kd + kk+16 + q*4); }
        }
        #pragma unroll
        for (int k = 0; k < 16; k++){
            float a[8], w[8];
            *(float4*)(a+0) = *(const float4*)&As[buf][k][tm*8+0];
            *(float4*)(a+4) = *(const float4*)&As[buf][k][tm*8+4];
            *(float4*)(w+0) = *(const float4*)&Ws[buf][k][tn*8+0];
            *(float4*)(w+4) = *(const float4*)&Ws[buf][k][tn*8+4];
            #pragma unroll
            for (int i = 0; i < 8; i++){
                #pragma unroll
                for (int j = 0; j < 8; j++)
                    acc[i][j] = fmaf(a[i], w[j], acc[i][j]);
            }
        }
        if (more){
            int nb = buf^1;
            { int row = tid>>2, q = tid&3;
              As[nb][q*4+0][row]=pa0.x; As[nb][q*4+1][row]=pa0.y; As[nb][q*4+2][row]=pa0.z; As[nb][q*4+3][row]=pa0.w;
              Ws[nb][q*4+0][row]=pw0.x; Ws[nb][q*4+1][row]=pw0.y; Ws[nb][q*4+2][row]=pw0.z; Ws[nb][q*4+3][row]=pw0.w; }
            { int f4 = tid + 256; int row = f4>>2, q = f4&3;
              As[nb][q*4+0][row]=pa1.x; As[nb][q*4+1][row]=pa1.y; As[nb][q*4+2][row]=pa1.z; As[nb][q*4+3][row]=pa1.w;
              Ws[nb][q*4+0][row]=pw1.x; Ws[nb][q*4+1][row]=pw1.y; Ws[nb][q*4+2][row]=pw1.z; Ws[nb][q*4+3][row]=pw1.w; }
            __syncthreads();
        }
    }
    float bv[8] = {0.f,0.f,0.f,0.f,0.f,0.f,0.f,0.f};
    if (bias){
        #pragma unroll
        for (int j = 0; j < 8; j++) bv[j] = bias[n0 + tn*8 + j];
    }
    #pragma unroll
    for (int i = 0; i < 8; i++){
        int m = m0 + tm*8 + i;
        float v[8];
        #pragma unroll
        for (int j = 0; j < 8; j++){
            v[j] = acc[i][j] + bv[j];
            if (act == 1) v[j] = geluf(v[j]);
        }
        float4* p = (float4*)(C + (size_t)m*Nq + n0 + tn*8);
        p[0] = make_float4(v[0], v[1], v[2], v[3]);
        p[1] = make_float4(v[4], v[5], v[6], v[7]);
    }
}

// ----- depthwise 3x3 conv + bias + SiLU, sliding-window; writes xcT AND u1t ---------------
__global__ void k_dwconv(const float* __restrict__ xz, const float* __restrict__ cw,
                         const float* __restrict__ cb, float* __restrict__ xcT,
                         float* __restrict__ u1t){
    int b = blockIdx.z, h = blockIdx.y, w0 = blockIdx.x<<5;
    int d = threadIdx.x;
    float wt[9];
    #pragma unroll
    for (int t2 = 0; t2 < 9; t2++) wt[t2] = __ldg(cw + d*9 + t2);
    float bi = __ldg(cb + d);
    int hm = h - 1, hp = h + 1;
    bool okm = (hm >= 0), okp = (hp < 128);
    const float* rowm = xz + ((size_t)(b*Ll + hm*128))*256 + d;
    const float* row0 = xz + ((size_t)(b*Ll + h *128))*256 + d;
    const float* rowp = xz + ((size_t)(b*Ll + hp*128))*256 + d;

    float a0[3], a1[3], a2[3];
    {
        int ww = w0 - 1;
        if (ww >= 0){
            a0[0] = okm ? rowm[(size_t)ww*256] : 0.f;
            a0[1] = row0[(size_t)ww*256];
            a0[2] = okp ? rowp[(size_t)ww*256] : 0.f;
        } else { a0[0]=a0[1]=a0[2]=0.f; }
    }
    {
        int ww = w0;
        a1[0] = okm ? rowm[(size_t)ww*256] : 0.f;
        a1[1] = row0[(size_t)ww*256];
        a1[2] = okp ? rowp[(size_t)ww*256] : 0.f;
    }
    for (int w = 0; w < 32; w++){
        int ww = w0 + w + 1;
        if (ww < 128){
            a2[0] = okm ? rowm[(size_t)ww*256] : 0.f;
            a2[1] = row0[(size_t)ww*256];
            a2[2] = okp ? rowp[(size_t)ww*256] : 0.f;
        } else { a2[0]=a2[1]=a2[2]=0.f; }
        float acc = bi;
        acc = fmaf(wt[0], a0[0], acc); acc = fmaf(wt[1], a1[0], acc); acc = fmaf(wt[2], a2[0], acc);
        acc = fmaf(wt[3], a0[1], acc); acc = fmaf(wt[4], a1[1], acc); acc = fmaf(wt[5], a2[1], acc);
        acc = fmaf(wt[6], a0[2], acc); acc = fmaf(wt[7], a1[2], acc); acc = fmaf(wt[8], a2[2], acc);
        acc = acc/(1.f + __expf(-acc));   // SiLU
        xcT[((size_t)(b*Ll + h*128 + w0 + w))*128 + d] = acc;
        u1t[((size_t)(b*Ll + (w0 + w)*128 + h))*128 + d] = acc;
        a0[0]=a1[0]; a0[1]=a1[1]; a0[2]=a1[2];
        a1[0]=a2[0]; a1[1]=a2[1]; a1[2]=a2[2];
    }
}

// -------- fused x_proj + scan pass 1: BC/dts to global, local scan from smem --------------
__global__ void k_xps(const float* __restrict__ xcT, const float* __restrict__ u1t,
                      const float* __restrict__ xpw,
                      const float* __restrict__ dtw, const float* __restrict__ dtb,
                      const float* __restrict__ Alogs,
                      float* __restrict__ bcbuf, float* __restrict__ dtsbuf,
                      float* __restrict__ sum){
    int k = blockIdx.y, b = blockIdx.z; int l0 = blockIdx.x*128;
    int chunk = blockIdx.x;
    __shared__ float Wp[36*128];
    __shared__ float UX[36*132];
    __shared__ float sB[LC*16];
    __shared__ float sdt[LC*4];
    int tid = threadIdx.x;
    const float* uptr = ((k&1) ? u1t : xcT) + (size_t)b*Ll*128;
    bool rev = (k >= 2);
    for (int e = tid; e < 36*128; e += 128) Wp[e] = xpw[(size_t)k*36*128 + e];

    int lt = tid & 31;
    int ct = tid >> 5;
    float acc[9][4] = {};

    for (int dc = 0; dc < 128; dc += 32){
        __syncthreads();
        #pragma unroll
        for (int rep = 0; rep < 8; rep++){
            int f4 = tid + rep*128;
            int l = f4>>3, dq = f4&7;
            int pos = l0 + l; int src = rev ? (Ll-1-pos) : pos;
            float4 uv = *(const float4*)(uptr + (size_t)src*128 + dc + dq*4);
            UX[(dq*4+0)*132 + l] = uv.x;
            UX[(dq*4+1)*132 + l] = uv.y;
            UX[(dq*4+2)*132 + l] = uv.z;
            UX[(dq*4+3)*132 + l] = uv.w;
        }
        __syncthreads();
        #pragma unroll 4
        for (int d2 = 0; d2 < 32; d2++){
            float4 uv = *(const float4*)&UX[d2*132 + lt*4];
            float wv[9];
            #pragma unroll
            for (int m = 0; m < 9; m++) wv[m] = Wp[(ct*9+m)*128 + dc + d2];
            #pragma unroll
            for (int m = 0; m < 9; m++){
                acc[m][0] = fmaf(wv[m], uv.x, acc[m][0]);
                acc[m][1] = fmaf(wv[m], uv.y, acc[m][1]);
                acc[m][2] = fmaf(wv[m], uv.z, acc[m][2]);
                acc[m][3] = fmaf(wv[m], uv.w, acc[m][3]);
            }
        }
    }
    __syncthreads();
    #pragma unroll
    for (int m = 0; m < 9; m++)
        *(float4*)&UX[(ct*9+m)*132 + lt*4] = *(float4*)acc[m];
    __syncthreads();
    size_t bcbase = ((size_t)(b*4+k)*Ll + l0)*32;
    for (int e = tid; e < 128*32; e += 128){
        int lo = e>>5, n = e&31;
        float v = UX[(4+n)*132 + lo];
        bcbuf[bcbase + (size_t)lo*32 + n] = v;
        if (n < 16) sB[lo*16 + n] = v;
    }
    size_t dtbase = ((size_t)(b*4+k)*Ll + l0)*4;
    for (int e = tid; e < 128*4; e += 128){
        int lo = e>>2, r = e&3;
        float v = UX[r*132 + lo];
        dtsbuf[dtbase + (size_t)lo*4 + r] = v;
        sdt[lo*4 + r] = v;
    }
    __syncthreads();

    // ---------------- scan pass 1 (local, h0 = 0) ----------------
    int d = tid;
    float Ahat[16];
    const float* Ap = Alogs + (size_t)(k*128+d)*16;
    #pragma unroll
    for (int n = 0; n < 16; n++) Ahat[n] = -expf(Ap[n]);
    bool geo = true;
    #pragma unroll
    for (int n = 0; n < 16; n++)
        geo = geo && (fabsf(Ahat[n] - (float)(n+1)*Ahat[0]) <= 1e-4f*fabsf(Ahat[n]));
    float4 wv = *(const float4*)(dtw + (size_t)k*512 + d*4);
    float bsv = dtb[k*128 + d];
    float h[16];
    #pragma unroll
    for (int n = 0; n < 16; n++) h[n] = 0.f;
    float S = 0.f;
    const float* ub = uptr + d;
    if (geo){
        float A0 = Ahat[0];
        #pragma unroll 2
        for (int t = 0; t < LC; t++){
            float4 q = *(const float4*)(sdt + t*4);
            float v = fmaf(wv.x,q.x, fmaf(wv.y,q.y, fmaf(wv.z,q.z, fmaf(wv.w,q.w, bsv))));
            float dv = (v > 20.f) ? v : __logf(1.f + __expf(v));
            int l = l0 + t; int ls = rev ? (Ll-1-l) : l;
            float uv = ub[(size_t)ls*128];
            float du = dv*uv;
            S += dv;
            float bb[16];
            *(float4*)(bb+0)  = *(const float4*)(sB + t*16 + 0);
            *(float4*)(bb+4)  = *(const float4*)(sB + t*16 + 4);
            *(float4*)(bb+8)  = *(const float4*)(sB + t*16 + 8);
            *(float4*)(bb+12) = *(const float4*)(sB + t*16 + 12);
            float p = __expf(dv*A0);
            float a = p;
            #pragma unroll
            for (int n = 0; n < 16; n++){
                h[n] = fmaf(a, h[n], du*bb[n]);
                a *= p;
            }
        }
    } else {
        #pragma unroll 2
        for (int t = 0; t < LC; t++){
            float4 q = *(const float4*)(sdt + t*4);
            float v = fmaf(wv.x,q.x, fmaf(wv.y,q.y, fmaf(wv.z,q.z, fmaf(wv.w,q.w, bsv))));
            float dv = (v > 20.f) ? v : __logf(1.f + __expf(v));
            int l = l0 + t; int ls = rev ? (Ll-1-l) : l;
            float uv = ub[(size_t)ls*128];
            float du = dv*uv;
            S += dv;
            float bb[16];
            *(float4*)(bb+0)  = *(const float4*)(sB + t*16 + 0);
            *(float4*)(bb+4)  = *(const float4*)(sB + t*16 + 4);
            *(float4*)(bb+8)  = *(const float4*)(sB + t*16 + 8);
            *(float4*)(bb+12) = *(const float4*)(sB + t*16 + 12);
            #pragma unroll
            for (int n = 0; n < 16; n++){
                float a = __expf(dv*Ahat[n]);
                h[n] = fmaf(a, h[n], du*bb[n]);
            }
        }
    }
    float* sp = sum + (((size_t)((b*4+k)*NC + chunk)*128 + d)*32);
    #pragma unroll
    for (int n = 0; n < 16; n++){ sp[n] = __expf(S*Ahat[n]); sp[16+n] = h[n]; }
}

// -------------------- scan pass 2: sequential combine, software-prefetched ---------------
__global__ void k_scan2(const float* __restrict__ sum, float* __restrict__ hinit){
    int tid = blockIdx.x*256 + threadIdx.x;   // 16384 threads: (kb, d, n)
    int n = tid & 15;
    int d = (tid>>4) & 127;
    int kb = tid>>11;
    size_t stride = 128*32;
    size_t base = ((size_t)kb*NC*128 + d)*32 + n;
    float* hp = hinit + ((size_t)kb*NC*128 + d)*16 + n;
    float h = 0.f;
    float Pv = sum[base];
    float hE = sum[base + 16];
    for (int c = 0; c < NC; c++){
        float Pn = 0.f, hn = 0.f;
        if (c + 1 < NC){
            Pn = sum[base + (size_t)(c+1)*stride];
            hn = sum[base + (size_t)(c+1)*stride + 16];
        }
        hp[(size_t)c*128*16] = h;
        h = Pv*h + hE;
        Pv = Pn; hE = hn;
    }
}

// -------------------- scan pass 3: full scan per chunk with true init, emit y ------------
__global__ void k_scan3(const float* __restrict__ xcT, const float* __restrict__ u1t,
                        const float* __restrict__ dts, const float* __restrict__ bc,
                        const float* __restrict__ dtw, const float* __restrict__ dtb,
                        const float* __restrict__ Alogs, const float* __restrict__ Ds,
                        const float* __restrict__ hinit, float* __restrict__ ys){
    int chunk = blockIdx.x, k = blockIdx.y, b = blockIdx.z;
    int d = threadIdx.x;
    __shared__ float sBC[LC*32];
    __shared__ float sdt[LC*4];
    int l0 = chunk*LC;
    const float4* bcp4 = (const float4*)(bc + ((size_t)(b*4+k)*Ll + l0)*32);
    for (int e = d; e < LC*8; e += 128) ((float4*)sBC)[e] = bcp4[e];
    ((float4*)sdt)[d] = ((const float4*)(dts + ((size_t)(b*4+k)*Ll + l0)*4))[d];
    __syncthreads();
    float Ahat[16];
    const float* Ap = Alogs + (size_t)(k*128+d)*16;
    #pragma unroll
    for (int n = 0; n < 16; n++) Ahat[n] = -expf(Ap[n]);
    bool geo = true;
    #pragma unroll
    for (int n = 0; n < 16; n++)
        geo = geo && (fabsf(Ahat[n] - (float)(n+1)*Ahat[0]) <= 1e-4f*fabsf(Ahat[n]));
    float4 wv = *(const float4*)(dtw + (size_t)k*512 + d*4);
    float bsv = dtb[k*128 + d];
    float Dv = Ds[k*128 + d];
    float h[16];
    const float* hi = hinit + ((size_t)((b*4+k)*NC + chunk)*128 + d)*16;
    #pragma unroll
    for (int n = 0; n < 16; n++) h[n] = hi[n];
    const float* ub = ((k&1) ? u1t : xcT) + (size_t)b*Ll*128 + d;
    float* yp = ys + ((size_t)(b*4+k)*Ll + l0)*128 + d;
    bool rev = (k >= 2);
    if (geo){
        float A0 = Ahat[0];
        #pragma unroll 2
        for (int t = 0; t < LC; t++){
            float4 q = *(const float4*)(sdt + t*4);
            float v = fmaf(wv.x,q.x, fmaf(wv.y,q.y, fmaf(wv.z,q.z, fmaf(wv.w,q.w, bsv))));
            float dv = (v > 20.f) ? v : __logf(1.f + __expf(v));
            int l = l0 + t; int ls = rev ? (Ll-1-l) : l;
            float uv = ub[(size_t)ls*128];
            float du = dv*uv;
            float bb[16], cc[16];
            const float4* rb = (const float4*)(sBC + t*32);
            *(float4*)(bb+0)=rb[0]; *(float4*)(bb+4)=rb[1]; *(float4*)(bb+8)=rb[2]; *(float4*)(bb+12)=rb[3];
            *(float4*)(cc+0)=rb[4]; *(float4*)(cc+4)=rb[5]; *(float4*)(cc+8)=rb[6]; *(float4*)(cc+12)=rb[7];
            float p = __expf(dv*A0);
            float a = p;
            float y0 = 0.f, y1 = 0.f;
            #pragma unroll
            for (int n = 0; n < 16; n += 2){
                h[n]   = fmaf(a, h[n],   du*bb[n]);   a *= p;
                h[n+1] = fmaf(a, h[n+1], du*bb[n+1]); a *= p;
                y0 = fmaf(h[n],   cc[n],   y0);
                y1 = fmaf(h[n+1], cc[n+1], y1);
            }
            yp[(size_t)t*128] = y0 + y1 + Dv*uv;
        }
    } else {
        #pragma unroll 2
        for (int t = 0; t < LC; t++){
            float4 q = *(const float4*)(sdt + t*4);
            float v = fmaf(wv.x,q.x, fmaf(wv.y,q.y, fmaf(wv.z,q.z, fmaf(wv.w,q.w, bsv))));
            float dv = (v > 20.f) ? v : __logf(1.f + __expf(v));
            int l = l0 + t; int ls = rev ? (Ll-1-l) : l;
            float uv = ub[(size_t)ls*128];
            float du = dv*uv;
            float bb[16], cc[16];
            const float4* rb = (const float4*)(sBC + t*32);
            *(float4*)(bb+0)=rb[0]; *(float4*)(bb+4)=rb[1]; *(float4*)(bb+8)=rb[2]; *(float4*)(bb+12)=rb[3];
            *(float4*)(cc+0)=rb[4]; *(float4*)(cc+4)=rb[5]; *(float4*)(cc+8)=rb[6]; *(float4*)(cc+12)=rb[7];
            float y0 = 0.f, y1 = 0.f;
            #pragma unroll
            for (int n = 0; n < 16; n += 2){
                float e0 = __expf(dv*Ahat[n]);
                float e1 = __expf(dv*Ahat[n+1]);
                h[n]   = fmaf(e0, h[n],   du*bb[n]);
                h[n+1] = fmaf(e1, h[n+1], du*bb[n+1]);
                y0 = fmaf(h[n],   cc[n],   y0);
                y1 = fmaf(h[n+1], cc[n+1], y1);
            }
            yp[(size_t)t*128] = y0 + y1 + Dv*uv;
        }
    }
}

// ---- fused cross-merge + out_norm(LN 128) * silu(z); warp-per-row, shfl-only -------------
__global__ void k_yo(const float* __restrict__ ys, const float* __restrict__ xz,
                     const float* __restrict__ g, const float* __restrict__ bb,
                     float* __restrict__ yo){
    int b = blockIdx.y;
    int warp = threadIdx.x>>5, lane = threadIdx.x&31;
    int l = blockIdx.x*8 + warp;
    int lT = ((l & 127) << 7) | (l >> 7);
    size_t st = (size_t)Ll*128;
    size_t base = (size_t)b*4*st;
    int d0 = lane*4;
    float4 v0 = *(const float4*)(ys + base        + (size_t)l*128         + d0);
    float4 v2 = *(const float4*)(ys + base + 2*st + (size_t)(Ll-1-l)*128  + d0);
    float4 v1 = *(const float4*)(ys + base + 1*st + (size_t)lT*128        + d0);
    float4 v3 = *(const float4*)(ys + base + 3*st + (size_t)(Ll-1-lT)*128 + d0);
    float4 v;
    v.x = (v0.x+v2.x)+(v1.x+v3.x);
    v.y = (v0.y+v2.y)+(v1.y+v3.y);
    v.z = (v0.z+v2.z)+(v1.z+v3.z);
    v.w = (v0.w+v2.w)+(v1.w+v3.w);
    float s  = (v.x+v.y)+(v.z+v.w);
    float s2 = (v.x*v.x+v.y*v.y)+(v.z*v.z+v.w*v.w);
    #pragma unroll
    for (int o = 16; o; o >>= 1){ s += __shfl_xor_sync(~0u, s, o); s2 += __shfl_xor_sync(~0u, s2, o); }
    float mean = s*(1.f/128.f);
    float rstd = rsqrtf(s2*(1.f/128.f) - mean*mean + 1e-5f);
    float4 gv = *(const float4*)(g + d0);
    float4 bv = *(const float4*)(bb + d0);
    float4 z  = *(const float4*)(xz + ((size_t)(b*Ll) + l)*256 + 128 + d0);
    float4 ov;
    ov.x = ((v.x-mean)*rstd*gv.x + bv.x) * (z.x/(1.f + __expf(-z.x)));
    ov.y = ((v.y-mean)*rstd*gv.y + bv.y) * (z.y/(1.f + __expf(-z.y)));
    ov.z = ((v.z-mean)*rstd*gv.z + bv.z) * (z.z/(1.f + __expf(-z.z)));
    ov.w = ((v.w-mean)*rstd*gv.w + bv.w) * (z.w/(1.f + __expf(-z.w)));
    *(float4*)(yo + ((size_t)(b*Ll) + l)*128 + d0) = ov;
}

// ------- head conv1: 64->32, 3x3, leaky; full-row blocks, 4w x 4oc per thread -------------
__global__ void __launch_bounds__(256) k_conv1(const float* __restrict__ t,
                                               const float* __restrict__ w1,
                                               float* __restrict__ o1){
    extern __shared__ float st[];
    int b = blockIdx.y, h = blockIdx.x;
    int tid = threadIdx.x;
    for (int e = tid; e < 3*130*16; e += 256){
        int c4 = e & 15;
        int wi = (e>>4) % 130;
        int r  = (e>>4) / 130;
        int hh = h + r - 1, ww = wi - 1;
        float4 v = make_float4(0.f,0.f,0.f,0.f);
        if ((unsigned)hh < 128u && (unsigned)ww < 128u)
            v = *(const float4*)(t + ((size_t)(b*Ll) + hh*128 + ww)*64 + c4*4);
        st[((size_t)r*64 + c4*4+0)*132 + wi] = v.x;
        st[((size_t)r*64 + c4*4+1)*132 + wi] = v.y;
        st[((size_t)r*64 + c4*4+2)*132 + wi] = v.z;
        st[((size_t)r*64 + c4*4+3)*132 + wi] = v.w;
    }
    __syncthreads();
    int wq = tid & 31;
    int og = tid >> 5;
    int wbase = wq*4;
    float acc[4][4] = {};
    #pragma unroll
    for (int kh = 0; kh < 3; kh++){
        for (int ic = 0; ic < 64; ic++){
            float in[8];
            const float* rowp = st + ((size_t)kh*64 + ic)*132;
            *(float4*)(in+0) = *(const float4*)(rowp + wbase);
            *(float4*)(in+4) = *(const float4*)(rowp + wbase + 4);
            #pragma unroll
            for (int kw = 0; kw < 3; kw++){
                float wt[4];
                #pragma unroll
                for (int j = 0; j < 4; j++)
                    wt[j] = __ldg(w1 + ((size_t)((og*4+j)*64 + ic))*9 + kh*3 + kw);
                #pragma unroll
                for (int j = 0; j < 4; j++){
                    acc[0][j] = fmaf(wt[j], in[0+kw], acc[0][j]);
                    acc[1][j] = fmaf(wt[j], in[1+kw], acc[1][j]);
                    acc[2][j] = fmaf(wt[j], in[2+kw], acc[2][j]);
                    acc[3][j] = fmaf(wt[j], in[3+kw], acc[3][j]);
                }
            }
        }
    }
    #pragma unroll
    for (int j = 0; j < 4; j++){
        #pragma unroll
        for (int w2 = 0; w2 < 4; w2++){
            float v = acc[w2][j];
            v = (v >= 0.f) ? v : 0.01f*v;
            o1[((size_t)(b*32 + og*4 + j))*Ll + h*128 + wbase + w2] = v;
        }
    }
}

// ------- head conv2: 32->1, 3x3, + img, sigmoid; full-row blocks, smem-staged -------------
__global__ void __launch_bounds__(128) k_conv2(const float* __restrict__ o1,
                                               const float* __restrict__ w2,
                                               const float* __restrict__ img,
                                               float* __restrict__ out){
    extern __shared__ float sc[];
    int b = blockIdx.y, h = blockIdx.x;
    int tid = threadIdx.x;
    for (int e = tid; e < 32*3*130; e += 128){
        int s = e % 130;
        int rc = e / 130;
        int r = rc % 3, ic = rc / 3;
        int hh = h + r - 1, ww = s - 1;
        float v = 0.f;
        if ((unsigned)hh < 128u && (unsigned)ww < 128u)
            v = o1[((size_t)(b*32 + ic))*Ll + hh*128 + ww];
        sc[((size_t)ic*3 + r)*132 + s] = v;
    }
    __syncthreads();
    int w = tid;
    float acc = 0.f;
    for (int ic = 0; ic < 32; ic++){
        #pragma unroll
        for (int kh = 0; kh < 3; kh++){
            const float* rowp = sc + ((size_t)ic*3 + kh)*132;
            float w0 = __ldg(w2 + ic*9 + kh*3 + 0);
            float w1v = __ldg(w2 + ic*9 + kh*3 + 1);
            float w2v = __ldg(w2 + ic*9 + kh*3 + 2);
            acc = fmaf(w0,  rowp[w+0], acc);
            acc = fmaf(w1v, rowp[w+1], acc);
            acc = fmaf(w2v, rowp[w+2], acc);
        }
    }
    int idx = (b<<14) + h*128 + w;
    float o = acc + img[idx];
    out[idx] = 1.f/(1.f + expf(-o));
}

// -------------------- launch --------------------
extern "C" void kernel_launch(void* const* d_in, const int* in_sizes, int n_in,
                              void* d_out, int out_size){
    const float* inp_img   = (const float*)d_in[0];
    const float* x         = (const float*)d_in[1];
    const float* y         = (const float*)d_in[2];
    const float* reduce_w  = (const float*)d_in[3];
    const float* patch_w   = (const float*)d_in[4];
    const float* patch_g   = (const float*)d_in[5];
    const float* patch_b   = (const float*)d_in[6];
    const float* ln1_g     = (const float*)d_in[7];
    const float* ln1_b     = (const float*)d_in[8];
    const float* in_proj_w = (const float*)d_in[9];
    const float* conv_w    = (const float*)d_in[10];
    const float* conv_b    = (const float*)d_in[11];
    const float* x_proj_w  = (const float*)d_in[12];
    const float* dt_proj_w = (const float*)d_in[13];
    const float* dt_proj_b = (const float*)d_in[14];
    const float* A_logs    = (const float*)d_in[15];
    const float* Ds_p      = (const float*)d_in[16];
    const float* out_norm_g= (const float*)d_in[17];
    const float* out_norm_b= (const float*)d_in[18];
    const float* out_proj_w= (const float*)d_in[19];
    const float* ln2_g     = (const float*)d_in[20];
    const float* ln2_b     = (const float*)d_in[21];
    const float* fc1_w     = (const float*)d_in[22];
    const float* fc1_b     = (const float*)d_in[23];
    const float* fc2_w     = (const float*)d_in[24];
    const float* fc2_b     = (const float*)d_in[25];
    const float* out1_w    = (const float*)d_in[26];
    const float* out2_w    = (const float*)d_in[27];

    float* out = (float*)d_out;
    float* f   = out + Bn*Ll;   // second output: f at offset 32768

    float *t, *h, *xz, *xcT, *u1t, *bcp, *dtsb, *ysb, *yob, *o1b, *sumb, *hib;
    cudaGetSymbolAddress((void**)&t,    g_t);
    cudaGetSymbolAddress((void**)&h,    g_h);
    cudaGetSymbolAddress((void**)&xz,   g_xz);
    cudaGetSymbolAddress((void**)&xcT,  g_xcT);
    cudaGetSymbolAddress((void**)&u1t,  g_u1t);
    cudaGetSymbolAddress((void**)&bcp,  g_bc);
    cudaGetSymbolAddress((void**)&dtsb, g_dts);
    cudaGetSymbolAddress((void**)&ysb,  g_ys);
    cudaGetSymbolAddress((void**)&yob,  g_yo);
    cudaGetSymbolAddress((void**)&o1b,  g_o1);
    cudaGetSymbolAddress((void**)&sumb, g_sum);
    cudaGetSymbolAddress((void**)&hib,  g_hinit);

    const int C1_SMEM = 3*64*132*4;    // 101376 bytes
    const int C2_SMEM = 32*3*132*4;    // 50688 bytes
    cudaFuncSetAttribute(k_conv1, cudaFuncAttributeMaxDynamicSharedMemorySize, C1_SMEM);
    cudaFuncSetAttribute(k_conv2, cudaFuncAttributeMaxDynamicSharedMemorySize, C2_SMEM);

    const int M = Bn*Ll;  // 32768

    k_reduce<<<dim3(512,2), 256>>>(x, y, reduce_w, f);
    k_patch <<<dim3(512,2), 256>>>(f, patch_w, h);
    k_ln64  <<<M/8, 256>>>(h, t, patch_g, patch_b);

    for (int i = 0; i < NB; i++){
        const float* dtw_i = dt_proj_w + (size_t)i*Kk*DI*4;
        const float* dtb_i = dt_proj_b + (size_t)i*Kk*DI;
        const float* Al_i  = A_logs   + (size_t)i*Kk*DI*16;
        if (i == 0)
            k_ln64 <<<M/8, 256>>>(t, h, ln1_g, ln1_b);
        k_gemm128<<<dim3(2,256), 256>>>(h, in_proj_w + (size_t)i*256*64, nullptr, xz,
                                        M, 256, 64, 0);
        k_dwconv <<<dim3(4,128,2), 128>>>(xz, conv_w + (size_t)i*DI*9, conv_b + i*DI, xcT, u1t);
        k_xps    <<<dim3(128,4,2), 128>>>(xcT, u1t, x_proj_w + (size_t)i*Kk*36*DI,
                                          dtw_i, dtb_i, Al_i, bcp, dtsb, sumb);
        k_scan2  <<<64, 256>>>(sumb, hib);
        k_scan3  <<<dim3(NC,Kk,Bn), 128>>>(xcT, u1t, dtsb, bcp, dtw_i, dtb_i, Al_i,
                                           Ds_p + (size_t)i*Kk*DI, hib, ysb);
        k_yo     <<<dim3(2048,Bn), 256>>>(ysb, xz, out_norm_g + i*128, out_norm_b + i*128, yob);
        // out_proj accumulate into t, fused LN2 -> h
        k_gemm   <<<dim3(1,256), 256>>>(yob, out_proj_w + (size_t)i*64*128, nullptr, t,
                                        M, 64, 128, 0, 1,
                                        ln2_g + i*64, ln2_b + i*64, h);
        // MLP: fc1 (+GELU) into xz, fc2 accumulate into t with fused next-LN1 -> h
        k_gemm128<<<dim3(2,256), 256>>>(h, fc1_w + (size_t)i*256*64, fc1_b + i*256, xz,
                                        M, 256, 64, 1);
        if (i < NB-1)
            k_gemm <<<dim3(1,256), 256>>>(xz, fc2_w + (size_t)i*64*256, fc2_b + i*64, t,
                                          M, 64, 256, 0, 1,
                                          ln1_g + (i+1)*64, ln1_b + (i+1)*64, h);
        else
            k_gemm <<<dim3(1,256), 256>>>(xz, fc2_w + (size_t)i*64*256, fc2_b + i*64, t,
                                          M, 64, 256, 0, 1,
                                          nullptr, nullptr, nullptr);
    }

    k_conv1<<<dim3(128,2), 256, C1_SMEM>>>(t, out1_w, o1b);
    k_conv2<<<dim3(128,2), 128, C2_SMEM>>>(o1b, out2_w, inp_img, out);
}

// round 16
// speedup vs baseline: 1.7821x; 1.0032x over previous
#include <cuda_runtime.h>
#include <math.h>

#define Bn 2
#define Ll 16384
#define DI 128
#define Kk 4
#define NB 4
#define NC 128          // chunks per sequence
#define LC 128          // chunk length

// -------------------- scratch (device globals; no allocation) --------------------
__device__ float g_t  [Bn*Ll*64];        // residual stream (b,l,64)
__device__ float g_h  [Bn*Ll*64];        // LN scratch (b,l,64)
__device__ float g_xz [Bn*Ll*256];       // in_proj out / MLP hidden (b,l,256)
__device__ float g_xcT[Bn*Ll*DI];        // conv+silu out, NHWC (b,l,d)
__device__ float g_u1t[Bn*Ll*DI];        // wh-order (b, w*128+h, d)
__device__ float g_bc [Bn*Kk*Ll*32];     // B(16)+C(16) per (b,k,l)
__device__ float g_dts[Bn*Kk*Ll*4];      // raw dt-rank values per (b,k,l)
__device__ float g_ys [(size_t)Bn*Kk*Ll*DI];   // (b,k,l,d)
__device__ float g_yo [Bn*Ll*DI];        // gated+LN (b,l,d)
__device__ float g_o1 [Bn*32*Ll];        // head conv1 out (b,32,l)
__device__ float g_sum  [Bn*Kk*NC*DI*32];  // per-chunk {P[16], hEnd[16]}
__device__ float g_hinit[Bn*Kk*NC*DI*16];  // per-chunk init state

__device__ __forceinline__ float geluf(float v){
    return 0.5f*v*(1.f + erff(v*0.70710678118654752f));
}

// -------------------- stem: f = 1x1 conv over concat(x,y) --------------------
__global__ void k_reduce(const float* __restrict__ x, const float* __restrict__ y,
                         const float* __restrict__ rw, float* __restrict__ f){
    __shared__ float sx[128][33];
    __shared__ float so[64][33];
    int b = blockIdx.y; int l0 = blockIdx.x*32;
    int tid = threadIdx.x;
    for (int e = tid; e < 128*32; e += 256){
        int c = e>>5, li = e&31;
        sx[c][li] = (c < 64) ? x[((size_t)(b*64+c))*Ll + l0+li]
                             : y[((size_t)(b*64+c-64))*Ll + l0+li];
    }
    __syncthreads();
    int o = tid>>2, lb = (tid&3)*8;
    float acc[8] = {0.f,0.f,0.f,0.f,0.f,0.f,0.f,0.f};
    for (int c = 0; c < 128; c++){
        float w = __ldg(rw + o*128 + c);
        #pragma unroll
        for (int j = 0; j < 8; j++) acc[j] += w*sx[c][lb+j];
    }
    #pragma unroll
    for (int j = 0; j < 8; j++) so[o][lb+j] = acc[j];
    __syncthreads();
    for (int e = tid; e < 64*32; e += 256){
        int oo = e>>5, li = e&31;
        f[((size_t)(b*64+oo))*Ll + l0+li] = so[oo][li];
    }
}

// -------------------- patch embed 1x1 conv (reads f), writes (b,l,64) --------------------
__global__ void k_patch(const float* __restrict__ f, const float* __restrict__ pw,
                        float* __restrict__ out){
    __shared__ float sx[64][33];
    __shared__ float so[64][33];
    int b = blockIdx.y; int l0 = blockIdx.x*32;
    int tid = threadIdx.x;
    for (int e = tid; e < 64*32; e += 256){
        int c = e>>5, li = e&31;
        sx[c][li] = f[((size_t)(b*64+c))*Ll + l0+li];
    }
    __syncthreads();
    int o = tid>>2, lb = (tid&3)*8;
    float acc[8] = {0.f,0.f,0.f,0.f,0.f,0.f,0.f,0.f};
    for (int c = 0; c < 64; c++){
        float w = __ldg(pw + o*64 + c);
        #pragma unroll
        for (int j = 0; j < 8; j++) acc[j] += w*sx[c][lb+j];
    }
    #pragma unroll
    for (int j = 0; j < 8; j++) so[o][lb+j] = acc[j];
    __syncthreads();
    for (int e = tid; e < 64*32; e += 256){
        int o2 = e&63, li = e>>6;
        out[((size_t)(b*Ll) + l0 + li)*64 + o2] = so[o2][li];
    }
}

// ------------- LayerNorm over last dim of 64; warp-per-row, shfl-only --------------------
__global__ void k_ln64(const float* __restrict__ in, float* __restrict__ out,
                       const float* __restrict__ g, const float* __restrict__ bb){
    int warp = threadIdx.x>>5, lane = threadIdx.x&31;
    size_t row = (size_t)blockIdx.x*8 + warp;
    float2 v = *(const float2*)(in + row*64 + lane*2);
    float s = v.x + v.y, s2 = v.x*v.x + v.y*v.y;
    #pragma unroll
    for (int o = 16; o; o >>= 1){ s += __shfl_xor_sync(~0u, s, o); s2 += __shfl_xor_sync(~0u, s2, o); }
    float mean = s*(1.f/64.f);
    float rstd = rsqrtf(s2*(1.f/64.f) - mean*mean + 1e-5f);
    float2 gg = *(const float2*)(g + lane*2);
    float2 bv = *(const float2*)(bb + lane*2);
    float2 ov;
    ov.x = (v.x-mean)*rstd*gg.x + bv.x;
    ov.y = (v.y-mean)*rstd*gg.y + bv.y;
    *(float2*)(out + row*64 + lane*2) = ov;
}

// ------ GEMM 128x64 tile, 8x4/thread, double-buffered; optional fused row-LN epilogue -----
__global__ void k_gemm(const float* __restrict__ A, const float* __restrict__ Wm,
                       const float* __restrict__ bias, float* __restrict__ C,
                       int M, int Nq, int Kd, int act, int accum,
                       const float* __restrict__ lng, const float* __restrict__ lnb,
                       float* __restrict__ lnout){
    __shared__ float As[2][16][132];
    __shared__ float Ws[2][16][68];
    int m0 = blockIdx.y<<7, n0 = blockIdx.x<<6;
    int tid = threadIdx.x;
    int tm = tid>>4, tn = tid&15;
    float acc[8][4] = {};

    {
        #pragma unroll
        for (int rep = 0; rep < 2; rep++){
            int f4 = tid + rep*256;
            int row = f4>>2, q = f4&3;
            float4 av = *(const float4*)(A + (size_t)(m0+row)*Kd + 0 + q*4);
            As[0][q*4+0][row]=av.x; As[0][q*4+1][row]=av.y; As[0][q*4+2][row]=av.z; As[0][q*4+3][row]=av.w;
        }
        int row = tid>>2, q = tid&3;
        float4 wv = *(const float4*)(Wm + (size_t)(n0+row)*Kd + 0 + q*4);
        Ws[0][q*4+0][row]=wv.x; Ws[0][q*4+1][row]=wv.y; Ws[0][q*4+2][row]=wv.z; Ws[0][q*4+3][row]=wv.w;
    }
    __syncthreads();

    int buf = 0;
    for (int kk = 0; kk < Kd; kk += 16, buf ^= 1){
        float4 pa0, pa1, pw;
        bool more = (kk + 16) < Kd;
        if (more){
            { int row = tid>>2, q = tid&3;
              pa0 = *(const float4*)(A + (size_t)(m0+row)*Kd + kk+16 + q*4); }
            { int f4 = tid + 256; int row = f4>>2, q = f4&3;
              pa1 = *(const float4*)(A + (size_t)(m0+row)*Kd + kk+16 + q*4); }
            { int row = tid>>2, q = tid&3;
              pw = *(const float4*)(Wm + (size_t)(n0+row)*Kd + kk+16 + q*4); }
        }
        #pragma unroll
        for (int k = 0; k < 16; k++){
            float a[8], w[4];
            *(float4*)(a+0) = *(const float4*)&As[buf][k][tm*8+0];
            *(float4*)(a+4) = *(const float4*)&As[buf][k][tm*8+4];
            *(float4*)(w+0) = *(const float4*)&Ws[buf][k][tn*4];
            #pragma unroll
            for (int i = 0; i < 8; i++){
                acc[i][0] = fmaf(a[i], w[0], acc[i][0]);
                acc[i][1] = fmaf(a[i], w[1], acc[i][1]);
                acc[i][2] = fmaf(a[i], w[2], acc[i][2]);
                acc[i][3] = fmaf(a[i], w[3], acc[i][3]);
            }
        }
        if (more){
            int nb = buf^1;
            { int row = tid>>2, q = tid&3;
              As[nb][q*4+0][row]=pa0.x; As[nb][q*4+1][row]=pa0.y; As[nb][q*4+2][row]=pa0.z; As[nb][q*4+3][row]=pa0.w; }
            { int f4 = tid + 256; int row = f4>>2, q = f4&3;
              As[nb][q*4+0][row]=pa1.x; As[nb][q*4+1][row]=pa1.y; As[nb][q*4+2][row]=pa1.z; As[nb][q*4+3][row]=pa1.w; }
            { int row = tid>>2, q = tid&3;
              Ws[nb][q*4+0][row]=pw.x; Ws[nb][q*4+1][row]=pw.y; Ws[nb][q*4+2][row]=pw.z; Ws[nb][q*4+3][row]=pw.w; }
            __syncthreads();
        }
    }
    float bv[4] = {0.f,0.f,0.f,0.f};
    if (bias){
        #pragma unroll
        for (int j = 0; j < 4; j++) bv[j] = bias[n0 + tn*4 + j];
    }
    float gv[4], gb[4];
    if (lng){
        #pragma unroll
        for (int j = 0; j < 4; j++){ gv[j] = lng[tn*4 + j]; gb[j] = lnb[tn*4 + j]; }
    }
    #pragma unroll
    for (int i = 0; i < 8; i++){
        int m = m0 + tm*8 + i;
        float4* p = (float4*)(C + (size_t)m*Nq + n0 + tn*4);
        float v0 = acc[i][0]+bv[0], v1 = acc[i][1]+bv[1], v2 = acc[i][2]+bv[2], v3 = acc[i][3]+bv[3];
        if (act == 1){ v0=geluf(v0); v1=geluf(v1); v2=geluf(v2); v3=geluf(v3); }
        if (accum){ float4 old = *p; v0+=old.x; v1+=old.y; v2+=old.z; v3+=old.w; }
        *p = make_float4(v0, v1, v2, v3);
        if (lng){
            float rs  = v0+v1+v2+v3;
            float rs2 = v0*v0+v1*v1+v2*v2+v3*v3;
            #pragma unroll
            for (int o = 1; o < 16; o <<= 1){
                rs  += __shfl_xor_sync(~0u, rs,  o);
                rs2 += __shfl_xor_sync(~0u, rs2, o);
            }
            float mean = rs*(1.f/64.f);
            float rstd = rsqrtf(rs2*(1.f/64.f) - mean*mean + 1e-5f);
            float4 hv;
            hv.x = (v0-mean)*rstd*gv[0] + gb[0];
            hv.y = (v1-mean)*rstd*gv[1] + gb[1];
            hv.z = (v2-mean)*rstd*gv[2] + gb[2];
            hv.w = (v3-mean)*rstd*gv[3] + gb[3];
            *(float4*)(lnout + (size_t)m*64 + tn*4) = hv;
        }
    }
}

// ------ GEMM 128x128 tile, 8x8 per thread, double-buffered (N multiple of 128) -----------
__global__ void __launch_bounds__(256) k_gemm128(
                       const float* __restrict__ A, const float* __restrict__ Wm,
                       const float* __restrict__ bias, float* __restrict__ C,
                       int M, int Nq, int Kd, int act){
    __shared__ float As[2][16][132];
    __shared__ float Ws[2][16][132];
    int m0 = blockIdx.y<<7, n0 = blockIdx.x<<7;
    int tid = threadIdx.x;
    int tm = tid>>4, tn = tid&15;
    float acc[8][8] = {};

    {
        #pragma unroll
        for (int rep = 0; rep < 2; rep++){
            int f4 = tid + rep*256;
            int row = f4>>2, q = f4&3;
            float4 av = *(const float4*)(A + (size_t)(m0+row)*Kd + 0 + q*4);
            As[0][q*4+0][row]=av.x; As[0][q*4+1][row]=av.y; As[0][q*4+2][row]=av.z; As[0][q*4+3][row]=av.w;
            float4 wv = *(const float4*)(Wm + (size_t)(n0+row)*Kd + 0 + q*4);
            Ws[0][q*4+0][row]=wv.x; Ws[0][q*4+1][row]=wv.y; Ws[0][q*4+2][row]=wv.z; Ws[0][q*4+3][row]=wv.w;
        }
    }
    __syncthreads();

    int buf = 0;
    for (int kk = 0; kk < Kd; kk += 16, buf ^= 1){
        float4 pa0, pa1, pw0, pw1;
        bool more = (kk + 16) < Kd;
        if (more){
            { int row = tid>>2, q = tid&3;
              pa0 = *(const float4*)(A  + (size_t)(m0+row)*Kd + kk+16 + q*4);
              pw0 = *(const float4*)(Wm + (size_t)(n0+row)*Kd + kk+16 + q*4); }
            { int f4 = tid + 256; int row = f4>>2, q = f4&3;
              pa1 = *(const float4*)(A  + (size_t)(m0+row)*Kd + kk+16 + q*4);
              pw1 = *(const float4*)(Wm + (size_t)(n0+row)*Kd + kk+16 + q*4); }
        }
        #pragma unroll
        for (int k = 0; k < 16; k++){
            float a[8], w[8];
            *(float4*)(a+0) = *(const float4*)&As[buf][k][tm*8+0];
            *(float4*)(a+4) = *(const float4*)&As[buf][k][tm*8+4];
            *(float4*)(w+0) = *(const float4*)&Ws[buf][k][tn*8+0];
            *(float4*)(w+4) = *(const float4*)&Ws[buf][k][tn*8+4];
            #pragma unroll
            for (int i = 0; i < 8; i++){
                #pragma unroll
                for (int j = 0; j < 8; j++)
                    acc[i][j] = fmaf(a[i], w[j], acc[i][j]);
            }
        }
        if (more){
            int nb = buf^1;
            { int row = tid>>2, q = tid&3;
              As[nb][q*4+0][row]=pa0.x; As[nb][q*4+1][row]=pa0.y; As[nb][q*4+2][row]=pa0.z; As[nb][q*4+3][row]=pa0.w;
              Ws[nb][q*4+0][row]=pw0.x; Ws[nb][q*4+1][row]=pw0.y; Ws[nb][q*4+2][row]=pw0.z; Ws[nb][q*4+3][row]=pw0.w; }
            { int f4 = tid + 256; int row = f4>>2, q = f4&3;
              As[nb][q*4+0][row]=pa1.x; As[nb][q*4+1][row]=pa1.y; As[nb][q*4+2][row]=pa1.z; As[nb][q*4+3][row]=pa1.w;
              Ws[nb][q*4+0][row]=pw1.x; Ws[nb][q*4+1][row]=pw1.y; Ws[nb][q*4+2][row]=pw1.z; Ws[nb][q*4+3][row]=pw1.w; }
            __syncthreads();
        }
    }
    float bv[8] = {0.f,0.f,0.f,0.f,0.f,0.f,0.f,0.f};
    if (bias){
        #pragma unroll
        for (int j = 0; j < 8; j++) bv[j] = bias[n0 + tn*8 + j];
    }
    #pragma unroll
    for (int i = 0; i < 8; i++){
        int m = m0 + tm*8 + i;
        float v[8];
        #pragma unroll
        for (int j = 0; j < 8; j++){
            v[j] = acc[i][j] + bv[j];
            if (act == 1) v[j] = geluf(v[j]);
        }
        float4* p = (float4*)(C + (size_t)m*Nq + n0 + tn*8);
        p[0] = make_float4(v[0], v[1], v[2], v[3]);
        p[1] = make_float4(v[4], v[5], v[6], v[7]);
    }
}

// ----- depthwise 3x3 conv + bias + SiLU, sliding-window; writes xcT AND u1t ---------------
__global__ void k_dwconv(const float* __restrict__ xz, const float* __restrict__ cw,
                         const float* __restrict__ cb, float* __restrict__ xcT,
                         float* __restrict__ u1t){
    int b = blockIdx.z, h = blockIdx.y, w0 = blockIdx.x<<5;
    int d = threadIdx.x;
    float wt[9];
    #pragma unroll
    for (int t2 = 0; t2 < 9; t2++) wt[t2] = __ldg(cw + d*9 + t2);
    float bi = __ldg(cb + d);
    int hm = h - 1, hp = h + 1;
    bool okm = (hm >= 0), okp = (hp < 128);
    const float* rowm = xz + ((size_t)(b*Ll + hm*128))*256 + d;
    const float* row0 = xz + ((size_t)(b*Ll + h *128))*256 + d;
    const float* rowp = xz + ((size_t)(b*Ll + hp*128))*256 + d;

    float a0[3], a1[3], a2[3];
    {
        int ww = w0 - 1;
        if (ww >= 0){
            a0[0] = okm ? rowm[(size_t)ww*256] : 0.f;
            a0[1] = row0[(size_t)ww*256];
            a0[2] = okp ? rowp[(size_t)ww*256] : 0.f;
        } else { a0[0]=a0[1]=a0[2]=0.f; }
    }
    {
        int ww = w0;
        a1[0] = okm ? rowm[(size_t)ww*256] : 0.f;
        a1[1] = row0[(size_t)ww*256];
        a1[2] = okp ? rowp[(size_t)ww*256] : 0.f;
    }
    for (int w = 0; w < 32; w++){
        int ww = w0 + w + 1;
        if (ww < 128){
            a2[0] = okm ? rowm[(size_t)ww*256] : 0.f;
            a2[1] = row0[(size_t)ww*256];
            a2[2] = okp ? rowp[(size_t)ww*256] : 0.f;
        } else { a2[0]=a2[1]=a2[2]=0.f; }
        float acc = bi;
        acc = fmaf(wt[0], a0[0], acc); acc = fmaf(wt[1], a1[0], acc); acc = fmaf(wt[2], a2[0], acc);
        acc = fmaf(wt[3], a0[1], acc); acc = fmaf(wt[4], a1[1], acc); acc = fmaf(wt[5], a2[1], acc);
        acc = fmaf(wt[6], a0[2], acc); acc = fmaf(wt[7], a1[2], acc); acc = fmaf(wt[8], a2[2], acc);
        acc = acc/(1.f + __expf(-acc));   // SiLU
        xcT[((size_t)(b*Ll + h*128 + w0 + w))*128 + d] = acc;
        u1t[((size_t)(b*Ll + (w0 + w)*128 + h))*128 + d] = acc;
        a0[0]=a1[0]; a0[1]=a1[1]; a0[2]=a1[2];
        a1[0]=a2[0]; a1[1]=a2[1]; a1[2]=a2[2];
    }
}

// -------- fused x_proj + scan pass 1: BC/dts to global, local scan from smem --------------
__global__ void k_xps(const float* __restrict__ xcT, const float* __restrict__ u1t,
                      const float* __restrict__ xpw,
                      const float* __restrict__ dtw, const float* __restrict__ dtb,
                      const float* __restrict__ Alogs,
                      float* __restrict__ bcbuf, float* __restrict__ dtsbuf,
                      float* __restrict__ sum){
    int k = blockIdx.y, b = blockIdx.z; int l0 = blockIdx.x*128;
    int chunk = blockIdx.x;
    __shared__ __align__(16) float Wp[36*128];
    __shared__ __align__(16) float UX[36*132];
    __shared__ __align__(16) float sB[LC*16];
    __shared__ __align__(16) float sdt[LC*4];
    int tid = threadIdx.x;
    const float* uptr = ((k&1) ? u1t : xcT) + (size_t)b*Ll*128;
    bool rev = (k >= 2);
    for (int e = tid; e < 36*128; e += 128) Wp[e] = xpw[(size_t)k*36*128 + e];

    int lt = tid & 31;
    int ct = tid >> 5;
    float acc[9][4] = {};

    for (int dc = 0; dc < 128; dc += 32){
        __syncthreads();
        #pragma unroll
        for (int rep = 0; rep < 8; rep++){
            int f4 = tid + rep*128;
            int l = f4>>3, dq = f4&7;
            int pos = l0 + l; int src = rev ? (Ll-1-pos) : pos;
            float4 uv = *(const float4*)(uptr + (size_t)src*128 + dc + dq*4);
            UX[(dq*4+0)*132 + l] = uv.x;
            UX[(dq*4+1)*132 + l] = uv.y;
            UX[(dq*4+2)*132 + l] = uv.z;
            UX[(dq*4+3)*132 + l] = uv.w;
        }
        __syncthreads();
        #pragma unroll
        for (int d2 = 0; d2 < 32; d2 += 4){
            // hoisted W loads: 9 x LDS.128 (warp-uniform broadcast)
            float4 wq[9];
            #pragma unroll
            for (int m = 0; m < 9; m++)
                wq[m] = *(const float4*)&Wp[(ct*9+m)*128 + dc + d2];
            #pragma unroll
            for (int j = 0; j < 4; j++){
                float4 uv = *(const float4*)&UX[(d2+j)*132 + lt*4];
                float wv;
                #pragma unroll
                for (int m = 0; m < 9; m++){
                    wv = (j==0) ? wq[m].x : (j==1) ? wq[m].y : (j==2) ? wq[m].z : wq[m].w;
                    acc[m][0] = fmaf(wv, uv.x, acc[m][0]);
                    acc[m][1] = fmaf(wv, uv.y, acc[m][1]);
                    acc[m][2] = fmaf(wv, uv.z, acc[m][2]);
                    acc[m][3] = fmaf(wv, uv.w, acc[m][3]);
                }
            }
        }
    }
    __syncthreads();
    #pragma unroll
    for (int m = 0; m < 9; m++)
        *(float4*)&UX[(ct*9+m)*132 + lt*4] = *(float4*)acc[m];
    __syncthreads();
    size_t bcbase = ((size_t)(b*4+k)*Ll + l0)*32;
    for (int e = tid; e < 128*32; e += 128){
        int lo = e>>5, n = e&31;
        float v = UX[(4+n)*132 + lo];
        bcbuf[bcbase + (size_t)lo*32 + n] = v;
        if (n < 16) sB[lo*16 + n] = v;
    }
    size_t dtbase = ((size_t)(b*4+k)*Ll + l0)*4;
    for (int e = tid; e < 128*4; e += 128){
        int lo = e>>2, r = e&3;
        float v = UX[r*132 + lo];
        dtsbuf[dtbase + (size_t)lo*4 + r] = v;
        sdt[lo*4 + r] = v;
    }
    __syncthreads();

    // ---------------- scan pass 1 (local, h0 = 0) ----------------
    int d = tid;
    float Ahat[16];
    const float* Ap = Alogs + (size_t)(k*128+d)*16;
    #pragma unroll
    for (int n = 0; n < 16; n++) Ahat[n] = -expf(Ap[n]);
    bool geo = true;
    #pragma unroll
    for (int n = 0; n < 16; n++)
        geo = geo && (fabsf(Ahat[n] - (float)(n+1)*Ahat[0]) <= 1e-4f*fabsf(Ahat[n]));
    float4 wv = *(const float4*)(dtw + (size_t)k*512 + d*4);
    float bsv = dtb[k*128 + d];
    float h[16];
    #pragma unroll
    for (int n = 0; n < 16; n++) h[n] = 0.f;
    float S = 0.f;
    const float* ub = uptr + d;
    if (geo){
        float A0 = Ahat[0];
        #pragma unroll 2
        for (int t = 0; t < LC; t++){
            float4 q = *(const float4*)(sdt + t*4);
            float v = fmaf(wv.x,q.x, fmaf(wv.y,q.y, fmaf(wv.z,q.z, fmaf(wv.w,q.w, bsv))));
            float dv = (v > 20.f) ? v : __logf(1.f + __expf(v));
            int l = l0 + t; int ls = rev ? (Ll-1-l) : l;
            float uv = ub[(size_t)ls*128];
            float du = dv*uv;
            S += dv;
            float bb[16];
            *(float4*)(bb+0)  = *(const float4*)(sB + t*16 + 0);
            *(float4*)(bb+4)  = *(const float4*)(sB + t*16 + 4);
            *(float4*)(bb+8)  = *(const float4*)(sB + t*16 + 8);
            *(float4*)(bb+12) = *(const float4*)(sB + t*16 + 12);
            float p = __expf(dv*A0);
            float a = p;
            #pragma unroll
            for (int n = 0; n < 16; n++){
                h[n] = fmaf(a, h[n], du*bb[n]);
                a *= p;
            }
        }
    } else {
        #pragma unroll 2
        for (int t = 0; t < LC; t++){
            float4 q = *(const float4*)(sdt + t*4);
            float v = fmaf(wv.x,q.x, fmaf(wv.y,q.y, fmaf(wv.z,q.z, fmaf(wv.w,q.w, bsv))));
            float dv = (v > 20.f) ? v : __logf(1.f + __expf(v));
            int l = l0 + t; int ls = rev ? (Ll-1-l) : l;
            float uv = ub[(size_t)ls*128];
            float du = dv*uv;
            S += dv;
            float bb[16];
            *(float4*)(bb+0)  = *(const float4*)(sB + t*16 + 0);
            *(float4*)(bb+4)  = *(const float4*)(sB + t*16 + 4);
            *(float4*)(bb+8)  = *(const float4*)(sB + t*16 + 8);
            *(float4*)(bb+12) = *(const float4*)(sB + t*16 + 12);
            #pragma unroll
            for (int n = 0; n < 16; n++){
                float a = __expf(dv*Ahat[n]);
                h[n] = fmaf(a, h[n], du*bb[n]);
            }
        }
    }
    float* sp = sum + (((size_t)((b*4+k)*NC + chunk)*128 + d)*32);
    #pragma unroll
    for (int n = 0; n < 16; n++){ sp[n] = __expf(S*Ahat[n]); sp[16+n] = h[n]; }
}

// -------------------- scan pass 2: sequential combine, software-prefetched ---------------
__global__ void k_scan2(const float* __restrict__ sum, float* __restrict__ hinit){
    int tid = blockIdx.x*256 + threadIdx.x;   // 16384 threads: (kb, d, n)
    int n = tid & 15;
    int d = (tid>>4) & 127;
    int kb = tid>>11;
    size_t stride = 128*32;
    size_t base = ((size_t)kb*NC*128 + d)*32 + n;
    float* hp = hinit + ((size_t)kb*NC*128 + d)*16 + n;
    float h = 0.f;
    float Pv = sum[base];
    float hE = sum[base + 16];
    for (int c = 0; c < NC; c++){
        float Pn = 0.f, hn = 0.f;
        if (c + 1 < NC){
            Pn = sum[base + (size_t)(c+1)*stride];
            hn = sum[base + (size_t)(c+1)*stride + 16];
        }
        hp[(size_t)c*128*16] = h;
        h = Pv*h + hE;
        Pv = Pn; hE = hn;
    }
}

// -------------------- scan pass 3: full scan per chunk with true init, emit y ------------
__global__ void k_scan3(const float* __restrict__ xcT, const float* __restrict__ u1t,
                        const float* __restrict__ dts, const float* __restrict__ bc,
                        const float* __restrict__ dtw, const float* __restrict__ dtb,
                        const float* __restrict__ Alogs, const float* __restrict__ Ds,
                        const float* __restrict__ hinit, float* __restrict__ ys){
    int chunk = blockIdx.x, k = blockIdx.y, b = blockIdx.z;
    int d = threadIdx.x;
    __shared__ float sBC[LC*32];
    __shared__ float sdt[LC*4];
    int l0 = chunk*LC;
    const float4* bcp4 = (const float4*)(bc + ((size_t)(b*4+k)*Ll + l0)*32);
    for (int e = d; e < LC*8; e += 128) ((float4*)sBC)[e] = bcp4[e];
    ((float4*)sdt)[d] = ((const float4*)(dts + ((size_t)(b*4+k)*Ll + l0)*4))[d];
    __syncthreads();
    float Ahat[16];
    const float* Ap = Alogs + (size_t)(k*128+d)*16;
    #pragma unroll
    for (int n = 0; n < 16; n++) Ahat[n] = -expf(Ap[n]);
    bool geo = true;
    #pragma unroll
    for (int n = 0; n < 16; n++)
        geo = geo && (fabsf(Ahat[n] - (float)(n+1)*Ahat[0]) <= 1e-4f*fabsf(Ahat[n]));
    float4 wv = *(const float4*)(dtw + (size_t)k*512 + d*4);
    float bsv = dtb[k*128 + d];
    float Dv = Ds[k*128 + d];
    float h[16];
    const float* hi = hinit + ((size_t)((b*4+k)*NC + chunk)*128 + d)*16;
    #pragma unroll
    for (int n = 0; n < 16; n++) h[n] = hi[n];
    const float* ub = ((k&1) ? u1t : xcT) + (size_t)b*Ll*128 + d;
    float* yp = ys + ((size_t)(b*4+k)*Ll + l0)*128 + d;
    bool rev = (k >= 2);
    if (geo){
        float A0 = Ahat[0];
        #pragma unroll 2
        for (int t = 0; t < LC; t++){
            float4 q = *(const float4*)(sdt + t*4);
            float v = fmaf(wv.x,q.x, fmaf(wv.y,q.y, fmaf(wv.z,q.z, fmaf(wv.w,q.w, bsv))));
            float dv = (v > 20.f) ? v : __logf(1.f + __expf(v));
            int l = l0 + t; int ls = rev ? (Ll-1-l) : l;
            float uv = ub[(size_t)ls*128];
            float du = dv*uv;
            float bb[16], cc[16];
            const float4* rb = (const float4*)(sBC + t*32);
            *(float4*)(bb+0)=rb[0]; *(float4*)(bb+4)=rb[1]; *(float4*)(bb+8)=rb[2]; *(float4*)(bb+12)=rb[3];
            *(float4*)(cc+0)=rb[4]; *(float4*)(cc+4)=rb[5]; *(float4*)(cc+8)=rb[6]; *(float4*)(cc+12)=rb[7];
            float p = __expf(dv*A0);
            float a = p;
            float y0 = 0.f, y1 = 0.f;
            #pragma unroll
            for (int n = 0; n < 16; n += 2){
                h[n]   = fmaf(a, h[n],   du*bb[n]);   a *= p;
                h[n+1] = fmaf(a, h[n+1], du*bb[n+1]); a *= p;
                y0 = fmaf(h[n],   cc[n],   y0);
                y1 = fmaf(h[n+1], cc[n+1], y1);
            }
            yp[(size_t)t*128] = y0 + y1 + Dv*uv;
        }
    } else {
        #pragma unroll 2
        for (int t = 0; t < LC; t++){
            float4 q = *(const float4*)(sdt + t*4);
            float v = fmaf(wv.x,q.x, fmaf(wv.y,q.y, fmaf(wv.z,q.z, fmaf(wv.w,q.w, bsv))));
            float dv = (v > 20.f) ? v : __logf(1.f + __expf(v));
            int l = l0 + t; int ls = rev ? (Ll-1-l) : l;
            float uv = ub[(size_t)ls*128];
            float du = dv*uv;
            float bb[16], cc[16];
            const float4* rb = (const float4*)(sBC + t*32);
            *(float4*)(bb+0)=rb[0]; *(float4*)(bb+4)=rb[1]; *(float4*)(bb+8)=rb[2]; *(float4*)(bb+12)=rb[3];
            *(float4*)(cc+0)=rb[4]; *(float4*)(cc+4)=rb[5]; *(float4*)(cc+8)=rb[6]; *(float4*)(cc+12)=rb[7];
            float y0 = 0.f, y1 = 0.f;
            #pragma unroll
            for (int n = 0; n < 16; n += 2){
                float e0 = __expf(dv*Ahat[n]);
                float e1 = __expf(dv*Ahat[n+1]);
                h[n]   = fmaf(e0, h[n],   du*bb[n]);
                h[n+1] = fmaf(e1, h[n+1], du*bb[n+1]);
                y0 = fmaf(h[n],   cc[n],   y0);
                y1 = fmaf(h[n+1], cc[n+1], y1);
            }
            yp[(size_t)t*128] = y0 + y1 + Dv*uv;
        }
    }
}

// ---- fused cross-merge + out_norm(LN 128) * silu(z); warp-per-row, shfl-only -------------
__global__ void k_yo(const float* __restrict__ ys, const float* __restrict__ xz,
                     const float* __restrict__ g, const float* __restrict__ bb,
                     float* __restrict__ yo){
    int b = blockIdx.y;
    int warp = threadIdx.x>>5, lane = threadIdx.x&31;
    int l = blockIdx.x*8 + warp;
    int lT = ((l & 127) << 7) | (l >> 7);
    size_t st = (size_t)Ll*128;
    size_t base = (size_t)b*4*st;
    int d0 = lane*4;
    float4 v0 = *(const float4*)(ys + base        + (size_t)l*128         + d0);
    float4 v2 = *(const float4*)(ys + base + 2*st + (size_t)(Ll-1-l)*128  + d0);
    float4 v1 = *(const float4*)(ys + base + 1*st + (size_t)lT*128        + d0);
    float4 v3 = *(const float4*)(ys + base + 3*st + (size_t)(Ll-1-lT)*128 + d0);
    float4 v;
    v.x = (v0.x+v2.x)+(v1.x+v3.x);
    v.y = (v0.y+v2.y)+(v1.y+v3.y);
    v.z = (v0.z+v2.z)+(v1.z+v3.z);
    v.w = (v0.w+v2.w)+(v1.w+v3.w);
    float s  = (v.x+v.y)+(v.z+v.w);
    float s2 = (v.x*v.x+v.y*v.y)+(v.z*v.z+v.w*v.w);
    #pragma unroll
    for (int o = 16; o; o >>= 1){ s += __shfl_xor_sync(~0u, s, o); s2 += __shfl_xor_sync(~0u, s2, o); }
    float mean = s*(1.f/128.f);
    float rstd = rsqrtf(s2*(1.f/128.f) - mean*mean + 1e-5f);
    float4 gv = *(const float4*)(g + d0);
    float4 bv = *(const float4*)(bb + d0);
    float4 z  = *(const float4*)(xz + ((size_t)(b*Ll) + l)*256 + 128 + d0);
    float4 ov;
    ov.x = ((v.x-mean)*rstd*gv.x + bv.x) * (z.x/(1.f + __expf(-z.x)));
    ov.y = ((v.y-mean)*rstd*gv.y + bv.y) * (z.y/(1.f + __expf(-z.y)));
    ov.z = ((v.z-mean)*rstd*gv.z + bv.z) * (z.z/(1.f + __expf(-z.z)));
    ov.w = ((v.w-mean)*rstd*gv.w + bv.w) * (z.w/(1.f + __expf(-z.w)));
    *(float4*)(yo + ((size_t)(b*Ll) + l)*128 + d0) = ov;
}

// ------- head conv1: 64->32, 3x3, leaky; full-row blocks, 4w x 4oc per thread -------------
__global__ void __launch_bounds__(256) k_conv1(const float* __restrict__ t,
                                               const float* __restrict__ w1,
                                               float* __restrict__ o1){
    extern __shared__ float st[];
    int b = blockIdx.y, h = blockIdx.x;
    int tid = threadIdx.x;
    for (int e = tid; e < 3*130*16; e += 256){
        int c4 = e & 15;
        int wi = (e>>4) % 130;
        int r  = (e>>4) / 130;
        int hh = h + r - 1, ww = wi - 1;
        float4 v = make_float4(0.f,0.f,0.f,0.f);
        if ((unsigned)hh < 128u && (unsigned)ww < 128u)
            v = *(const float4*)(t + ((size_t)(b*Ll) + hh*128 + ww)*64 + c4*4);
        st[((size_t)r*64 + c4*4+0)*132 + wi] = v.x;
        st[((size_t)r*64 + c4*4+1)*132 + wi] = v.y;
        st[((size_t)r*64 + c4*4+2)*132 + wi] = v.z;
        st[((size_t)r*64 + c4*4+3)*132 + wi] = v.w;
    }
    __syncthreads();
    int wq = tid & 31;
    int og = tid >> 5;
    int wbase = wq*4;
    float acc[4][4] = {};
    #pragma unroll
    for (int kh = 0; kh < 3; kh++){
        for (int ic = 0; ic < 64; ic++){
            float in[8];
            const float* rowp = st + ((size_t)kh*64 + ic)*132;
            *(float4*)(in+0) = *(const float4*)(rowp + wbase);
            *(float4*)(in+4) = *(const float4*)(rowp + wbase + 4);
            #pragma unroll
            for (int kw = 0; kw < 3; kw++){
                float wt[4];
                #pragma unroll
                for (int j = 0; j < 4; j++)
                    wt[j] = __ldg(w1 + ((size_t)((og*4+j)*64 + ic))*9 + kh*3 + kw);
                #pragma unroll
                for (int j = 0; j < 4; j++){
                    acc[0][j] = fmaf(wt[j], in[0+kw], acc[0][j]);
                    acc[1][j] = fmaf(wt[j], in[1+kw], acc[1][j]);
                    acc[2][j] = fmaf(wt[j], in[2+kw], acc[2][j]);
                    acc[3][j] = fmaf(wt[j], in[3+kw], acc[3][j]);
                }
            }
        }
    }
    #pragma unroll
    for (int j = 0; j < 4; j++){
        #pragma unroll
        for (int w2 = 0; w2 < 4; w2++){
            float v = acc[w2][j];
            v = (v >= 0.f) ? v : 0.01f*v;
            o1[((size_t)(b*32 + og*4 + j))*Ll + h*128 + wbase + w2] = v;
        }
    }
}

// ------- head conv2: 32->1, 3x3, + img, sigmoid; full-row blocks, smem-staged -------------
__global__ void __launch_bounds__(128) k_conv2(const float* __restrict__ o1,
                                               const float* __restrict__ w2,
                                               const float* __restrict__ img,
                                               float* __restrict__ out){
    extern __shared__ float sc[];
    int b = blockIdx.y, h = blockIdx.x;
    int tid = threadIdx.x;
    for (int e = tid; e < 32*3*130; e += 128){
        int s = e % 130;
        int rc = e / 130;
        int r = rc % 3, ic = rc / 3;
        int hh = h + r - 1, ww = s - 1;
        float v = 0.f;
        if ((unsigned)hh < 128u && (unsigned)ww < 128u)
            v = o1[((size_t)(b*32 + ic))*Ll + hh*128 + ww];
        sc[((size_t)ic*3 + r)*132 + s] = v;
    }
    __syncthreads();
    int w = tid;
    float acc = 0.f;
    for (int ic = 0; ic < 32; ic++){
        #pragma unroll
        for (int kh = 0; kh < 3; kh++){
            const float* rowp = sc + ((size_t)ic*3 + kh)*132;
            float w0 = __ldg(w2 + ic*9 + kh*3 + 0);
            float w1v = __ldg(w2 + ic*9 + kh*3 + 1);
            float w2v = __ldg(w2 + ic*9 + kh*3 + 2);
            acc = fmaf(w0,  rowp[w+0], acc);
            acc = fmaf(w1v, rowp[w+1], acc);
            acc = fmaf(w2v, rowp[w+2], acc);
        }
    }
    int idx = (b<<14) + h*128 + w;
    float o = acc + img[idx];
    out[idx] = 1.f/(1.f + expf(-o));
}

// -------------------- launch --------------------
extern "C" void kernel_launch(void* const* d_in, const int* in_sizes, int n_in,
                              void* d_out, int out_size){
    const float* inp_img   = (const float*)d_in[0];
    const float* x         = (const float*)d_in[1];
    const float* y         = (const float*)d_in[2];
    const float* reduce_w  = (const float*)d_in[3];
    const float* patch_w   = (const float*)d_in[4];
    const float* patch_g   = (const float*)d_in[5];
    const float* patch_b   = (const float*)d_in[6];
    const float* ln1_g     = (const float*)d_in[7];
    const float* ln1_b     = (const float*)d_in[8];
    const float* in_proj_w = (const float*)d_in[9];
    const float* conv_w    = (const float*)d_in[10];
    const float* conv_b    = (const float*)d_in[11];
    const float* x_proj_w  = (const float*)d_in[12];
    const float* dt_proj_w = (const float*)d_in[13];
    const float* dt_proj_b = (const float*)d_in[14];
    const float* A_logs    = (const float*)d_in[15];
    const float* Ds_p      = (const float*)d_in[16];
    const float* out_norm_g= (const float*)d_in[17];
    const float* out_norm_b= (const float*)d_in[18];
    const float* out_proj_w= (const float*)d_in[19];
    const float* ln2_g     = (const float*)d_in[20];
    const float* ln2_b     = (const float*)d_in[21];
    const float* fc1_w     = (const float*)d_in[22];
    const float* fc1_b     = (const float*)d_in[23];
    const float* fc2_w     = (const float*)d_in[24];
    const float* fc2_b     = (const float*)d_in[25];
    const float* out1_w    = (const float*)d_in[26];
    const float* out2_w    = (const float*)d_in[27];

    float* out = (float*)d_out;
    float* f   = out + Bn*Ll;   // second output: f at offset 32768

    float *t, *h, *xz, *xcT, *u1t, *bcp, *dtsb, *ysb, *yob, *o1b, *sumb, *hib;
    cudaGetSymbolAddress((void**)&t,    g_t);
    cudaGetSymbolAddress((void**)&h,    g_h);
    cudaGetSymbolAddress((void**)&xz,   g_xz);
    cudaGetSymbolAddress((void**)&xcT,  g_xcT);
    cudaGetSymbolAddress((void**)&u1t,  g_u1t);
    cudaGetSymbolAddress((void**)&bcp,  g_bc);
    cudaGetSymbolAddress((void**)&dtsb, g_dts);
    cudaGetSymbolAddress((void**)&ysb,  g_ys);
    cudaGetSymbolAddress((void**)&yob,  g_yo);
    cudaGetSymbolAddress((void**)&o1b,  g_o1);
    cudaGetSymbolAddress((void**)&sumb, g_sum);
    cudaGetSymbolAddress((void**)&hib,  g_hinit);

    const int C1_SMEM = 3*64*132*4;    // 101376 bytes
    const int C2_SMEM = 32*3*132*4;    // 50688 bytes
    cudaFuncSetAttribute(k_conv1, cudaFuncAttributeMaxDynamicSharedMemorySize, C1_SMEM);
    cudaFuncSetAttribute(k_conv2, cudaFuncAttributeMaxDynamicSharedMemorySize, C2_SMEM);

    const int M = Bn*Ll;  // 32768

    k_reduce<<<dim3(512,2), 256>>>(x, y, reduce_w, f);
    k_patch <<<dim3(512,2), 256>>>(f, patch_w, h);
    k_ln64  <<<M/8, 256>>>(h, t, patch_g, patch_b);

    for (int i = 0; i < NB; i++){
        const float* dtw_i = dt_proj_w + (size_t)i*Kk*DI*4;
        const float* dtb_i = dt_proj_b + (size_t)i*Kk*DI;
        const float* Al_i  = A_logs   + (size_t)i*Kk*DI*16;
        if (i == 0)
            k_ln64 <<<M/8, 256>>>(t, h, ln1_g, ln1_b);
        k_gemm128<<<dim3(2,256), 256>>>(h, in_proj_w + (size_t)i*256*64, nullptr, xz,
                                        M, 256, 64, 0);
        k_dwconv <<<dim3(4,128,2), 128>>>(xz, conv_w + (size_t)i*DI*9, conv_b + i*DI, xcT, u1t);
        k_xps    <<<dim3(128,4,2), 128>>>(xcT, u1t, x_proj_w + (size_t)i*Kk*36*DI,
                                          dtw_i, dtb_i, Al_i, bcp, dtsb, sumb);
        k_scan2  <<<64, 256>>>(sumb, hib);
        k_scan3  <<<dim3(NC,Kk,Bn), 128>>>(xcT, u1t, dtsb, bcp, dtw_i, dtb_i, Al_i,
                                           Ds_p + (size_t)i*Kk*DI, hib, ysb);
        k_yo     <<<dim3(2048,Bn), 256>>>(ysb, xz, out_norm_g + i*128, out_norm_b + i*128, yob);
        // out_proj accumulate into t, fused LN2 -> h
        k_gemm   <<<dim3(1,256), 256>>>(yob, out_proj_w + (size_t)i*64*128, nullptr, t,
                                        M, 64, 128, 0, 1,
                                        ln2_g + i*64, ln2_b + i*64, h);
        // MLP: fc1 (+GELU) into xz, fc2 accumulate into t with fused next-LN1 -> h
        k_gemm128<<<dim3(2,256), 256>>>(h, fc1_w + (size_t)i*256*64, fc1_b + i*256, xz,
                                        M, 256, 64, 1);
        if (i < NB-1)
            k_gemm <<<dim3(1,256), 256>>>(xz, fc2_w + (size_t)i*64*256, fc2_b + i*64, t,
                                          M, 64, 256, 0, 1,
                                          ln1_g + (i+1)*64, ln1_b + (i+1)*64, h);
        else
            k_gemm <<<dim3(1,256), 256>>>(xz, fc2_w + (size_t)i*64*256, fc2_b + i*64, t,
                                          M, 64, 256, 0, 1,
                                          nullptr, nullptr, nullptr);
    }

    k_conv1<<<dim3(128,2), 256, C1_SMEM>>>(t, out1_w, o1b);
    k_conv2<<<dim3(128,2), 128, C2_SMEM>>>(o1b, out2_w, inp_img, out);
}